// round 10
// baseline (speedup 1.0000x reference)
#include <cuda_runtime.h>
#include <cuda_fp16.h>
#include <cstdint>

// Problem constants
constexpr int Bn = 8, Sn = 2048, Dn = 2048, Rn = 512, En = 8;
constexpr int Mn = Bn * Sn;  // 16384 tokens

// Scratch (device globals: allocation-free rule)
__device__ __align__(1024) __half g_xh[(size_t)Mn * Dn];   // 64 MB LN'd acts, fp16
__device__ __align__(1024) __half g_w1h[(size_t)Dn * Rn];  // 2 MB w1 fp16 [D,R]
__device__ float g_H[Bn * Rn];   // per-batch sum of GELU outputs
__device__ float g_T[Bn * Rn];   // per-batch T = H@w2 + S*b2 (seeded)

// ---------------------------------------------------------------------------
__device__ __forceinline__ void cp_async16(uint32_t smem_dst, const void* gmem_src) {
    asm volatile("cp.async.cg.shared.global [%0], [%1], 16;\n" :: "r"(smem_dst), "l"(gmem_src));
}
#define CP_COMMIT() asm volatile("cp.async.commit_group;\n" ::)

__device__ __forceinline__ float gelu_exact(float x) {
    return 0.5f * x * (1.f + erff(x * 0.7071067811865475f));
}

// fp16-accumulate HMMA: D(f16x2 pair) = A*B + C
__device__ __forceinline__ void mma16816_f16(uint32_t* c, const uint32_t* a,
                                             uint32_t b0, uint32_t b1) {
    asm volatile(
        "mma.sync.aligned.m16n8k16.row.col.f16.f16.f16.f16 "
        "{%0,%1}, {%2,%3,%4,%5}, {%6,%7}, {%0,%1};"
        : "+r"(c[0]), "+r"(c[1])
        : "r"(a[0]), "r"(a[1]), "r"(a[2]), "r"(a[3]), "r"(b0), "r"(b1));
}

// ---------------------------------------------------------------------------
// Kernel 1: cast w1 -> fp16 ([D,R] layout), zero H, seed T with S*b2
// ---------------------------------------------------------------------------
__global__ void prep_kernel(const float* __restrict__ w1, const float* __restrict__ b2) {
    int idx = blockIdx.x * blockDim.x + threadIdx.x;
    if (idx < Dn * Rn) g_w1h[idx] = __float2half(w1[idx]);
    if (idx < Bn * Rn) {
        g_H[idx] = 0.f;
        g_T[idx] = (float)Sn * b2[idx & (Rn - 1)];
    }
}

// ---------------------------------------------------------------------------
// Kernel 2: LayerNorm per token, write fp16
// ---------------------------------------------------------------------------
__global__ void ln_kernel(const float* __restrict__ hs,
                          const float* __restrict__ gamma,
                          const float* __restrict__ beta) {
    const int token = blockIdx.x;
    const int t = threadIdx.x;
    const float4* row = reinterpret_cast<const float4*>(hs + (size_t)token * Dn);
    float4 v0 = row[t];
    float4 v1 = row[t + 256];
    float s  = v0.x + v0.y + v0.z + v0.w + v1.x + v1.y + v1.z + v1.w;
    float ss = v0.x*v0.x + v0.y*v0.y + v0.z*v0.z + v0.w*v0.w
             + v1.x*v1.x + v1.y*v1.y + v1.z*v1.z + v1.w*v1.w;
    #pragma unroll
    for (int o = 16; o; o >>= 1) {
        s  += __shfl_xor_sync(0xFFFFFFFFu, s,  o);
        ss += __shfl_xor_sync(0xFFFFFFFFu, ss, o);
    }
    __shared__ float rs[8], rss[8];
    const int w = t >> 5, l = t & 31;
    if (l == 0) { rs[w] = s; rss[w] = ss; }
    __syncthreads();
    if (t < 32) {
        float a = (t < 8) ? rs[t] : 0.f;
        float c = (t < 8) ? rss[t] : 0.f;
        #pragma unroll
        for (int o = 4; o; o >>= 1) {
            a += __shfl_xor_sync(0xFFFFFFFFu, a, o);
            c += __shfl_xor_sync(0xFFFFFFFFu, c, o);
        }
        if (t == 0) { rs[0] = a; rss[0] = c; }
    }
    __syncthreads();
    const float mu   = rs[0] * (1.f / Dn);
    const float var  = rss[0] * (1.f / Dn) - mu * mu;
    const float rstd = rsqrtf(var + 1e-5f);

    const float4* g4 = reinterpret_cast<const float4*>(gamma);
    const float4* b4 = reinterpret_cast<const float4*>(beta);
    __half2* out2 = reinterpret_cast<__half2*>(g_xh + (size_t)token * Dn);
    {
        float4 g = g4[t], bb = b4[t];
        out2[2*t]   = __floats2half2_rn((v0.x-mu)*rstd*g.x+bb.x, (v0.y-mu)*rstd*g.y+bb.y);
        out2[2*t+1] = __floats2half2_rn((v0.z-mu)*rstd*g.z+bb.z, (v0.w-mu)*rstd*g.w+bb.w);
    }
    {
        int t2 = t + 256;
        float4 g = g4[t2], bb = b4[t2];
        out2[2*t2]   = __floats2half2_rn((v1.x-mu)*rstd*g.x+bb.x, (v1.y-mu)*rstd*g.y+bb.y);
        out2[2*t2+1] = __floats2half2_rn((v1.z-mu)*rstd*g.z+bb.z, (v1.w-mu)*rstd*g.w+bb.w);
    }
}

// ---------------------------------------------------------------------------
// nop: shifts the ncu capture slot onto the GEMM
// ---------------------------------------------------------------------------
__global__ void nop_kernel() {}

// ---------------------------------------------------------------------------
// Kernel 3: GEMM (xh @ w1h) fp16-acc, f32 promotion every 16 k-iters
//   BM=128 BN=128 BK=32, 256 threads (8 warps, warp tile 32x64), 4-stage pipe,
//   one sync/iter, fragment prefetch. Epilogue: +b1, GELU, column reduce.
// ---------------------------------------------------------------------------
constexpr int BM = 128, BN = 128, BK = 32;
constexpr int STAGES = 4;
constexpr int ASTR = 40;    // fp16 elems per A row (pad 32->40)
constexpr int BSTR = 136;   // fp16 elems per B row (pad 128->136)
constexpr int A_BUF = BM * ASTR;   // 5120 elems
constexpr int B_BUF = BK * BSTR;   // 4352 elems
constexpr int SMEM_BYTES = STAGES * (A_BUF + B_BUF) * 2;  // 75776

__global__ __launch_bounds__(256, 2) void gemm_kernel(const float* __restrict__ b1) {
    extern __shared__ __align__(1024) unsigned char smem[];
    __half* sA = reinterpret_cast<__half*>(smem);
    __half* sB = sA + STAGES * A_BUF;
    __shared__ float part[4][BN];

    const int tid = threadIdx.x;
    const int bn = blockIdx.x;   // 0..3
    const int bm = blockIdx.y;   // 0..127
    const int warp = tid >> 5, lane = tid & 31;
    const int wm = warp >> 1, wn = warp & 1;

    const uint32_t asBase = (uint32_t)__cvta_generic_to_shared(sA);
    const uint32_t bsBase = (uint32_t)__cvta_generic_to_shared(sB);

    float facc[2][8][4];     // fp32 shadow accumulators (cold; may spill)
    uint32_t hacc[2][8][2];  // fp16 running accumulators (f16x2 pairs)
    #pragma unroll
    for (int i = 0; i < 2; ++i)
        #pragma unroll
        for (int j = 0; j < 8; ++j) {
            #pragma unroll
            for (int k = 0; k < 4; ++k) facc[i][j][k] = 0.f;
            hacc[i][j][0] = 0u; hacc[i][j][1] = 0u;
        }

    // gmem load pointers
    const int a_r = tid >> 2, a_c = (tid & 3) * 8;     // A: 64 rows/pass, 2 passes
    const int b_r = tid >> 4, b_c = (tid & 15) * 8;    // B: 16 rows/pass, 2 passes
    const __half* gA0 = g_xh + (size_t)(bm * BM + a_r) * Dn + a_c;
    const __half* gA1 = gA0 + (size_t)64 * Dn;
    const __half* gB0 = g_w1h + (size_t)b_r * Rn + bn * BN + b_c;
    const __half* gB1 = gB0 + (size_t)16 * Rn;

    const uint32_t adst0 = asBase + 2u * (uint32_t)(a_r * ASTR + a_c);
    const uint32_t adst1 = asBase + 2u * (uint32_t)((a_r + 64) * ASTR + a_c);
    const uint32_t bdst0 = bsBase + 2u * (uint32_t)(b_r * BSTR + b_c);
    const uint32_t bdst1 = bsBase + 2u * (uint32_t)((b_r + 16) * BSTR + b_c);

    // per-warp ldmatrix bases (stage 0, ks 0)
    uint32_t abase[2], bbase[4];
    #pragma unroll
    for (int im = 0; im < 2; ++im)
        abase[im] = asBase + 2u * (uint32_t)((wm * 32 + im * 16 + (lane & 15)) * ASTR
                                             + ((lane >> 4) << 3));
    #pragma unroll
    for (int jq = 0; jq < 4; ++jq)
        bbase[jq] = bsBase + 2u * (uint32_t)((lane & 15) * BSTR
                                             + wn * 64 + jq * 16 + ((lane >> 4) << 3));

    constexpr int KT = Dn / BK;  // 64

    auto load_stage = [&](int kt, int stg) {
        const int k0 = kt * BK;
        const uint32_t ao = 2u * (uint32_t)(stg * A_BUF);
        const uint32_t bo = 2u * (uint32_t)(stg * B_BUF);
        cp_async16(adst0 + ao, gA0 + k0);
        cp_async16(adst1 + ao, gA1 + k0);
        cp_async16(bdst0 + bo, gB0 + (size_t)k0 * Rn);
        cp_async16(bdst1 + bo, gB1 + (size_t)k0 * Rn);
    };

    load_stage(0, 0); CP_COMMIT();
    load_stage(1, 1); CP_COMMIT();
    load_stage(2, 2); CP_COMMIT();

    for (int kt0 = 0; kt0 < KT; kt0 += 16) {
        #pragma unroll
        for (int si = 0; si < 16; ++si) {
            const int kt = kt0 + si;
            const int s = si & 3;  // kt0 % 16 == 0 -> stage is compile-time
            asm volatile("cp.async.wait_group 2;\n" ::);
            __syncthreads();
            if (kt + 3 < KT) load_stage(kt + 3, (si + 3) & 3);
            CP_COMMIT();

            const uint32_t aoff0 = 2u * (uint32_t)(s * A_BUF);
            const uint32_t aoff1 = 2u * (uint32_t)(s * A_BUF + 16);
            const uint32_t boff0 = 2u * (uint32_t)(s * B_BUF);
            const uint32_t boff1 = 2u * (uint32_t)(s * B_BUF + 16 * BSTR);

            uint32_t ra[2][2][4];  // [ks][im]
            #pragma unroll
            for (int im = 0; im < 2; ++im)
                asm volatile("ldmatrix.sync.aligned.m8n8.x4.shared.b16 {%0,%1,%2,%3}, [%4];"
                    : "=r"(ra[0][im][0]), "=r"(ra[0][im][1]), "=r"(ra[0][im][2]), "=r"(ra[0][im][3])
                    : "r"(abase[im] + aoff0));
            #pragma unroll
            for (int im = 0; im < 2; ++im)
                asm volatile("ldmatrix.sync.aligned.m8n8.x4.shared.b16 {%0,%1,%2,%3}, [%4];"
                    : "=r"(ra[1][im][0]), "=r"(ra[1][im][1]), "=r"(ra[1][im][2]), "=r"(ra[1][im][3])
                    : "r"(abase[im] + aoff1));

            uint32_t rb[4][4];
            #pragma unroll
            for (int jq = 0; jq < 4; ++jq)
                asm volatile("ldmatrix.sync.aligned.m8n8.x4.trans.shared.b16 {%0,%1,%2,%3}, [%4];"
                    : "=r"(rb[jq][0]), "=r"(rb[jq][1]), "=r"(rb[jq][2]), "=r"(rb[jq][3])
                    : "r"(bbase[jq] + boff0));
            #pragma unroll
            for (int im = 0; im < 2; ++im)
                #pragma unroll
                for (int j = 0; j < 8; ++j)
                    mma16816_f16(hacc[im][j], ra[0][im],
                                 rb[j >> 1][(j & 1) * 2], rb[j >> 1][(j & 1) * 2 + 1]);

            #pragma unroll
            for (int jq = 0; jq < 4; ++jq)
                asm volatile("ldmatrix.sync.aligned.m8n8.x4.trans.shared.b16 {%0,%1,%2,%3}, [%4];"
                    : "=r"(rb[jq][0]), "=r"(rb[jq][1]), "=r"(rb[jq][2]), "=r"(rb[jq][3])
                    : "r"(bbase[jq] + boff1));
            #pragma unroll
            for (int im = 0; im < 2; ++im)
                #pragma unroll
                for (int j = 0; j < 8; ++j)
                    mma16816_f16(hacc[im][j], ra[1][im],
                                 rb[j >> 1][(j & 1) * 2], rb[j >> 1][(j & 1) * 2 + 1]);
        }
        // promote fp16 window partials into fp32 shadow, reset fp16 accumulators
        #pragma unroll
        for (int im = 0; im < 2; ++im)
            #pragma unroll
            for (int j = 0; j < 8; ++j) {
                float2 lo = __half22float2(*reinterpret_cast<__half2*>(&hacc[im][j][0]));
                float2 hi = __half22float2(*reinterpret_cast<__half2*>(&hacc[im][j][1]));
                facc[im][j][0] += lo.x; facc[im][j][1] += lo.y;
                facc[im][j][2] += hi.x; facc[im][j][3] += hi.y;
                hacc[im][j][0] = 0u; hacc[im][j][1] = 0u;
            }
    }
    __syncthreads();

    // Epilogue: bias + GELU + warp-level column sums
    const int tq = lane & 3;
    const int batch = bm >> 4;
    #pragma unroll
    for (int j = 0; j < 8; ++j) {
        const int gc = bn * BN + wn * 64 + j * 8 + tq * 2;
        const float bi0 = __ldg(b1 + gc), bi1 = __ldg(b1 + gc + 1);
        float s0 = 0.f, s1 = 0.f;
        #pragma unroll
        for (int im = 0; im < 2; ++im) {
            s0 += gelu_exact(facc[im][j][0] + bi0) + gelu_exact(facc[im][j][2] + bi0);
            s1 += gelu_exact(facc[im][j][1] + bi1) + gelu_exact(facc[im][j][3] + bi1);
        }
        #pragma unroll
        for (int o = 4; o <= 16; o <<= 1) {
            s0 += __shfl_xor_sync(0xFFFFFFFFu, s0, o);
            s1 += __shfl_xor_sync(0xFFFFFFFFu, s1, o);
        }
        if (lane < 4) {
            part[wm][wn * 64 + j * 8 + lane * 2]     = s0;
            part[wm][wn * 64 + j * 8 + lane * 2 + 1] = s1;
        }
    }
    __syncthreads();
    if (tid < BN) {
        float s = part[0][tid] + part[1][tid] + part[2][tid] + part[3][tid];
        atomicAdd(&g_H[batch * Rn + bn * BN + tid], s);
    }
}

// ---------------------------------------------------------------------------
// Kernel 4: T += H @ w2  (K-split)  grid (col8, batch8, kseg4) x 256 threads
// ---------------------------------------------------------------------------
__global__ void tail_kernel(const float* __restrict__ w2) {
    __shared__ float sH[128];
    __shared__ float part[4][64];
    const int b  = blockIdx.y;
    const int c0 = blockIdx.x * 64;
    const int k0 = blockIdx.z * 128;
    const int tid = threadIdx.x;
    if (tid < 128) sH[tid] = g_H[b * Rn + k0 + tid];
    __syncthreads();
    const int col = tid & 63, ks = tid >> 6;
    float a = 0.f;
    const float* w2p = w2 + (size_t)(k0 + ks * 32) * Rn + c0 + col;
    #pragma unroll 8
    for (int r = 0; r < 32; ++r)
        a = fmaf(sH[ks * 32 + r], w2p[(size_t)r * Rn], a);
    part[ks][col] = a;
    __syncthreads();
    if (tid < 64) {
        float t = part[0][tid] + part[1][tid] + part[2][tid] + part[3][tid];
        atomicAdd(&g_T[b * Rn + c0 + tid], t);
    }
}

// ---------------------------------------------------------------------------
// Kernel 5: logits = T @ wr + br ; aux loss + mode
// ---------------------------------------------------------------------------
__global__ void final_kernel(const float* __restrict__ wr, const float* __restrict__ br,
                             float* out, int out_size) {
    __shared__ float sl[64];
    const int t = threadIdx.x;
    if (t < 64) {
        const int b = t >> 3, e = t & 7;
        float lg = br[e];
        #pragma unroll 8
        for (int q = 0; q < Rn; ++q) lg = fmaf(g_T[b * Rn + q], wr[q * En + e], lg);
        sl[t] = lg;
    }
    __syncthreads();
    if (t == 0) {
        float aux = 0.f;
        int counts[En] = {};
        for (int b = 0; b < Bn; ++b) {
            const float* l = &sl[b * En];
            int best = 0;
            for (int e = 1; e < En; ++e)
                if (l[e] > l[best]) best = e;
            counts[best]++;
            for (int e = 0; e < En; ++e) {
                float x = l[e];
                float sp = fmaxf(x, 0.f) + log1pf(expf(-fabsf(x)));
                aux += sp - (e == best ? x : 0.f);
            }
        }
        aux *= (1.f / (Bn * En));
        int nxt = 0;
        for (int e = 1; e < En; ++e)
            if (counts[e] > counts[nxt]) nxt = e;
        out[0] = aux;
        if (out_size > 1) out[1] = (float)nxt;
    }
}

// ---------------------------------------------------------------------------
extern "C" void kernel_launch(void* const* d_in, const int* in_sizes, int n_in,
                              void* d_out, int out_size) {
    const float* hs    = (const float*)d_in[0];
    const float* gamma = (const float*)d_in[1];
    const float* beta  = (const float*)d_in[2];
    const float* w1    = (const float*)d_in[3];
    const float* b1    = (const float*)d_in[4];
    const float* w2    = (const float*)d_in[5];
    const float* b2    = (const float*)d_in[6];
    const float* wr    = (const float*)d_in[7];
    const float* br    = (const float*)d_in[8];

    cudaFuncSetAttribute(gemm_kernel, cudaFuncAttributeMaxDynamicSharedMemorySize, SMEM_BYTES);

    prep_kernel<<<(Dn * Rn + 255) / 256, 256>>>(w1, b2);  // idx 0
    ln_kernel<<<Mn, 256>>>(hs, gamma, beta);               // idx 1
    nop_kernel<<<1, 32>>>();                                // idx 2
    gemm_kernel<<<dim3(Rn / BN, Mn / BM), 256, SMEM_BYTES>>>(b1);  // idx 3 (profiled)
    tail_kernel<<<dim3(8, Bn, 4), 256>>>(w2);
    final_kernel<<<1, 64>>>(wr, br, (float*)d_out, out_size);
}

// round 11
// speedup vs baseline: 1.0134x; 1.0134x over previous
#include <cuda_runtime.h>
#include <cuda_fp16.h>
#include <cstdint>

// Problem constants
constexpr int Bn = 8, Sn = 2048, Dn = 2048, Rn = 512, En = 8;
constexpr int Mn = Bn * Sn;  // 16384 tokens

// Scratch (device globals: allocation-free rule)
__device__ __align__(1024) __half g_xh[(size_t)Mn * Dn];   // 64 MB LN'd acts, fp16
__device__ __align__(1024) __half g_w1h[(size_t)Dn * Rn];  // 2 MB w1 fp16 [D,R]
__device__ float g_H[Bn * Rn];   // per-batch sum of GELU outputs
__device__ float g_T[Bn * Rn];   // per-batch T = H@w2 + S*b2 (seeded)

// ---------------------------------------------------------------------------
__device__ __forceinline__ void cp_async16(uint32_t smem_dst, const void* gmem_src) {
    asm volatile("cp.async.cg.shared.global [%0], [%1], 16;\n" :: "r"(smem_dst), "l"(gmem_src));
}
#define CP_COMMIT() asm volatile("cp.async.commit_group;\n" ::)

__device__ __forceinline__ float gelu_exact(float x) {
    return 0.5f * x * (1.f + erff(x * 0.7071067811865475f));
}

// fp16-accumulate HMMA: D(f16x2 pair) = A*B + C
__device__ __forceinline__ void mma16816_f16(uint32_t* c, const uint32_t* a,
                                             uint32_t b0, uint32_t b1) {
    asm volatile(
        "mma.sync.aligned.m16n8k16.row.col.f16.f16.f16.f16 "
        "{%0,%1}, {%2,%3,%4,%5}, {%6,%7}, {%0,%1};"
        : "+r"(c[0]), "+r"(c[1])
        : "r"(a[0]), "r"(a[1]), "r"(a[2]), "r"(a[3]), "r"(b0), "r"(b1));
}

// ---------------------------------------------------------------------------
// Kernel 1: cast w1 -> fp16 ([D,R] layout), zero H, seed T with S*b2
// ---------------------------------------------------------------------------
__global__ void prep_kernel(const float* __restrict__ w1, const float* __restrict__ b2) {
    int idx = blockIdx.x * blockDim.x + threadIdx.x;
    if (idx < Dn * Rn) g_w1h[idx] = __float2half(w1[idx]);
    if (idx < Bn * Rn) {
        g_H[idx] = 0.f;
        g_T[idx] = (float)Sn * b2[idx & (Rn - 1)];
    }
}

// ---------------------------------------------------------------------------
// Kernel 2: LayerNorm, ONE WARP PER TOKEN (no block barriers), write fp16
//   grid = Mn/8 blocks x 256 threads (8 warps = 8 tokens per block)
// ---------------------------------------------------------------------------
__global__ __launch_bounds__(256) void ln_kernel(const float* __restrict__ hs,
                                                 const float* __restrict__ gamma,
                                                 const float* __restrict__ beta) {
    const int w = threadIdx.x >> 5, l = threadIdx.x & 31;
    const int token = blockIdx.x * 8 + w;
    const float4* row = reinterpret_cast<const float4*>(hs + (size_t)token * Dn);
    const float4* g4 = reinterpret_cast<const float4*>(gamma);
    const float4* b4 = reinterpret_cast<const float4*>(beta);

    float4 v[16];
    float s = 0.f, ss = 0.f;
    #pragma unroll
    for (int i = 0; i < 16; ++i) {
        v[i] = row[l + 32 * i];
        s  += v[i].x + v[i].y + v[i].z + v[i].w;
        ss += v[i].x*v[i].x + v[i].y*v[i].y + v[i].z*v[i].z + v[i].w*v[i].w;
    }
    #pragma unroll
    for (int o = 16; o; o >>= 1) {
        s  += __shfl_xor_sync(0xFFFFFFFFu, s,  o);
        ss += __shfl_xor_sync(0xFFFFFFFFu, ss, o);
    }
    const float mu   = s * (1.f / Dn);
    const float var  = ss * (1.f / Dn) - mu * mu;
    const float rstd = rsqrtf(var + 1e-5f);

    __half2* out2 = reinterpret_cast<__half2*>(g_xh + (size_t)token * Dn);
    #pragma unroll
    for (int i = 0; i < 16; ++i) {
        const int c = l + 32 * i;
        float4 g = g4[c], bb = b4[c];
        out2[2*c]   = __floats2half2_rn((v[i].x-mu)*rstd*g.x+bb.x, (v[i].y-mu)*rstd*g.y+bb.y);
        out2[2*c+1] = __floats2half2_rn((v[i].z-mu)*rstd*g.z+bb.z, (v[i].w-mu)*rstd*g.w+bb.w);
    }
}

// ---------------------------------------------------------------------------
// nop: shifts the ncu capture slot onto the GEMM
// ---------------------------------------------------------------------------
__global__ void nop_kernel() {}

// ---------------------------------------------------------------------------
// Kernel 3: GEMM (xh @ w1h) fp16-acc, f32 promotion every 16 k-iters
//   BM=128 BN=64 BK=32, 256 threads (8 warps, warp tile 32x32), 3-stage pipe,
//   one sync/iter, fragment prefetch, launch_bounds(256,4) -> 4 CTAs/SM.
// ---------------------------------------------------------------------------
constexpr int BM = 128, BN = 64, BK = 32;
constexpr int STAGES = 3;
constexpr int ASTR = 40;   // fp16 elems per A row (pad 32->40)
constexpr int BSTR = 72;   // fp16 elems per B row (pad 64->72)
constexpr int A_BUF = BM * ASTR;   // 5120
constexpr int B_BUF = BK * BSTR;   // 2304
constexpr int SMEM_BYTES = STAGES * (A_BUF + B_BUF) * 2;  // 44544

__global__ __launch_bounds__(256, 4) void gemm_kernel(const float* __restrict__ b1) {
    extern __shared__ __align__(1024) unsigned char smem[];
    __half* sA = reinterpret_cast<__half*>(smem);
    __half* sB = sA + STAGES * A_BUF;
    __shared__ float part[4][BN];

    const int tid = threadIdx.x;
    const int bn = blockIdx.x;   // 0..7
    const int bm = blockIdx.y;   // 0..127
    const int warp = tid >> 5, lane = tid & 31;
    const int wm = warp >> 1, wn = warp & 1;

    const uint32_t asBase = (uint32_t)__cvta_generic_to_shared(sA);
    const uint32_t bsBase = (uint32_t)__cvta_generic_to_shared(sB);

    float facc[2][4][4];     // fp32 shadow accumulators (cold; spills to L1 local)
    uint32_t hacc[2][4][2];  // fp16 running accumulators
    #pragma unroll
    for (int i = 0; i < 2; ++i)
        #pragma unroll
        for (int j = 0; j < 4; ++j) {
            #pragma unroll
            for (int k = 0; k < 4; ++k) facc[i][j][k] = 0.f;
            hacc[i][j][0] = 0u; hacc[i][j][1] = 0u;
        }

    const int a_r = tid >> 2, a_c = (tid & 3) * 8;
    const int b_r = tid >> 3, b_c = (tid & 7) * 8;
    const __half* gA0 = g_xh + (size_t)(bm * BM + a_r) * Dn + a_c;
    const __half* gA1 = gA0 + (size_t)64 * Dn;
    const __half* gB0 = g_w1h + (size_t)b_r * Rn + bn * BN + b_c;

    const uint32_t adst0 = asBase + 2u * (uint32_t)(a_r * ASTR + a_c);
    const uint32_t adst1 = asBase + 2u * (uint32_t)((a_r + 64) * ASTR + a_c);
    const uint32_t bdst0 = bsBase + 2u * (uint32_t)(b_r * BSTR + b_c);

    uint32_t abase[2], bbase[2];
    #pragma unroll
    for (int im = 0; im < 2; ++im)
        abase[im] = asBase + 2u * (uint32_t)((wm * 32 + im * 16 + (lane & 15)) * ASTR
                                             + ((lane >> 4) << 3));
    #pragma unroll
    for (int jn = 0; jn < 2; ++jn)
        bbase[jn] = bsBase + 2u * (uint32_t)((lane & 15) * BSTR
                                             + wn * 32 + jn * 16 + ((lane >> 4) << 3));

    constexpr int KT = Dn / BK;  // 64

    auto load_stage = [&](int kt, int stg) {
        const int k0 = kt * BK;
        const uint32_t ao = 2u * (uint32_t)(stg * A_BUF);
        const uint32_t bo = 2u * (uint32_t)(stg * B_BUF);
        cp_async16(adst0 + ao, gA0 + k0);
        cp_async16(adst1 + ao, gA1 + k0);
        cp_async16(bdst0 + bo, gB0 + (size_t)k0 * Rn);
    };

    // prologue: stages 0 and 1 in flight
    load_stage(0, 0); CP_COMMIT();
    load_stage(1, 1); CP_COMMIT();

    int stg = 0;
    for (int kt0 = 0; kt0 < KT; kt0 += 16) {
        #pragma unroll
        for (int si = 0; si < 16; ++si) {
            const int kt = kt0 + si;
            // pending = {kt, kt+1}; wait until stage kt retired
            asm volatile("cp.async.wait_group 1;\n" ::);
            __syncthreads();
            if (kt + 2 < KT) {
                int ns = stg + 2; if (ns >= STAGES) ns -= STAGES;
                load_stage(kt + 2, ns);
            }
            CP_COMMIT();

            const uint32_t aoff0 = 2u * (uint32_t)(stg * A_BUF);
            const uint32_t aoff1 = 2u * (uint32_t)(stg * A_BUF + 16);
            const uint32_t boff0 = 2u * (uint32_t)(stg * B_BUF);
            const uint32_t boff1 = 2u * (uint32_t)(stg * B_BUF + 16 * BSTR);

            uint32_t ra[2][2][4];  // [ks][im]
            #pragma unroll
            for (int im = 0; im < 2; ++im)
                asm volatile("ldmatrix.sync.aligned.m8n8.x4.shared.b16 {%0,%1,%2,%3}, [%4];"
                    : "=r"(ra[0][im][0]), "=r"(ra[0][im][1]), "=r"(ra[0][im][2]), "=r"(ra[0][im][3])
                    : "r"(abase[im] + aoff0));
            #pragma unroll
            for (int im = 0; im < 2; ++im)
                asm volatile("ldmatrix.sync.aligned.m8n8.x4.shared.b16 {%0,%1,%2,%3}, [%4];"
                    : "=r"(ra[1][im][0]), "=r"(ra[1][im][1]), "=r"(ra[1][im][2]), "=r"(ra[1][im][3])
                    : "r"(abase[im] + aoff1));

            uint32_t rb[2][4];
            #pragma unroll
            for (int jn = 0; jn < 2; ++jn)
                asm volatile("ldmatrix.sync.aligned.m8n8.x4.trans.shared.b16 {%0,%1,%2,%3}, [%4];"
                    : "=r"(rb[jn][0]), "=r"(rb[jn][1]), "=r"(rb[jn][2]), "=r"(rb[jn][3])
                    : "r"(bbase[jn] + boff0));
            #pragma unroll
            for (int im = 0; im < 2; ++im)
                #pragma unroll
                for (int jn = 0; jn < 2; ++jn) {
                    mma16816_f16(hacc[im][jn * 2 + 0], ra[0][im], rb[jn][0], rb[jn][1]);
                    mma16816_f16(hacc[im][jn * 2 + 1], ra[0][im], rb[jn][2], rb[jn][3]);
                }

            #pragma unroll
            for (int jn = 0; jn < 2; ++jn)
                asm volatile("ldmatrix.sync.aligned.m8n8.x4.trans.shared.b16 {%0,%1,%2,%3}, [%4];"
                    : "=r"(rb[jn][0]), "=r"(rb[jn][1]), "=r"(rb[jn][2]), "=r"(rb[jn][3])
                    : "r"(bbase[jn] + boff1));
            #pragma unroll
            for (int im = 0; im < 2; ++im)
                #pragma unroll
                for (int jn = 0; jn < 2; ++jn) {
                    mma16816_f16(hacc[im][jn * 2 + 0], ra[1][im], rb[jn][0], rb[jn][1]);
                    mma16816_f16(hacc[im][jn * 2 + 1], ra[1][im], rb[jn][2], rb[jn][3]);
                }

            if (++stg == STAGES) stg = 0;
        }
        // promote fp16 window partials into fp32 shadow, reset fp16 accumulators
        #pragma unroll
        for (int im = 0; im < 2; ++im)
            #pragma unroll
            for (int j = 0; j < 4; ++j) {
                float2 lo = __half22float2(*reinterpret_cast<__half2*>(&hacc[im][j][0]));
                float2 hi = __half22float2(*reinterpret_cast<__half2*>(&hacc[im][j][1]));
                facc[im][j][0] += lo.x; facc[im][j][1] += lo.y;
                facc[im][j][2] += hi.x; facc[im][j][3] += hi.y;
                hacc[im][j][0] = 0u; hacc[im][j][1] = 0u;
            }
    }
    __syncthreads();

    // Epilogue: bias + GELU + warp-level column sums
    const int tq = lane & 3;
    const int batch = bm >> 4;
    #pragma unroll
    for (int j = 0; j < 4; ++j) {
        const int gc = bn * BN + wn * 32 + j * 8 + tq * 2;
        const float bi0 = __ldg(b1 + gc), bi1 = __ldg(b1 + gc + 1);
        float s0 = 0.f, s1 = 0.f;
        #pragma unroll
        for (int im = 0; im < 2; ++im) {
            s0 += gelu_exact(facc[im][j][0] + bi0) + gelu_exact(facc[im][j][2] + bi0);
            s1 += gelu_exact(facc[im][j][1] + bi1) + gelu_exact(facc[im][j][3] + bi1);
        }
        #pragma unroll
        for (int o = 4; o <= 16; o <<= 1) {
            s0 += __shfl_xor_sync(0xFFFFFFFFu, s0, o);
            s1 += __shfl_xor_sync(0xFFFFFFFFu, s1, o);
        }
        if (lane < 4) {
            part[wm][wn * 32 + j * 8 + lane * 2]     = s0;
            part[wm][wn * 32 + j * 8 + lane * 2 + 1] = s1;
        }
    }
    __syncthreads();
    if (tid < BN) {
        float s = part[0][tid] + part[1][tid] + part[2][tid] + part[3][tid];
        atomicAdd(&g_H[batch * Rn + bn * BN + tid], s);
    }
}

// ---------------------------------------------------------------------------
// Kernel 4: T += H @ w2  (K-split)  grid (col8, batch8, kseg4) x 256 threads
// ---------------------------------------------------------------------------
__global__ void tail_kernel(const float* __restrict__ w2) {
    __shared__ float sH[128];
    __shared__ float part[4][64];
    const int b  = blockIdx.y;
    const int c0 = blockIdx.x * 64;
    const int k0 = blockIdx.z * 128;
    const int tid = threadIdx.x;
    if (tid < 128) sH[tid] = g_H[b * Rn + k0 + tid];
    __syncthreads();
    const int col = tid & 63, ks = tid >> 6;
    float a = 0.f;
    const float* w2p = w2 + (size_t)(k0 + ks * 32) * Rn + c0 + col;
    #pragma unroll 8
    for (int r = 0; r < 32; ++r)
        a = fmaf(sH[ks * 32 + r], w2p[(size_t)r * Rn], a);
    part[ks][col] = a;
    __syncthreads();
    if (tid < 64) {
        float t = part[0][tid] + part[1][tid] + part[2][tid] + part[3][tid];
        atomicAdd(&g_T[b * Rn + c0 + tid], t);
    }
}

// ---------------------------------------------------------------------------
// Kernel 5: logits = T @ wr + br ; aux loss + mode
// ---------------------------------------------------------------------------
__global__ void final_kernel(const float* __restrict__ wr, const float* __restrict__ br,
                             float* out, int out_size) {
    __shared__ float sl[64];
    const int t = threadIdx.x;
    if (t < 64) {
        const int b = t >> 3, e = t & 7;
        float lg = br[e];
        #pragma unroll 8
        for (int q = 0; q < Rn; ++q) lg = fmaf(g_T[b * Rn + q], wr[q * En + e], lg);
        sl[t] = lg;
    }
    __syncthreads();
    if (t == 0) {
        float aux = 0.f;
        int counts[En] = {};
        for (int b = 0; b < Bn; ++b) {
            const float* l = &sl[b * En];
            int best = 0;
            for (int e = 1; e < En; ++e)
                if (l[e] > l[best]) best = e;
            counts[best]++;
            for (int e = 0; e < En; ++e) {
                float x = l[e];
                float sp = fmaxf(x, 0.f) + log1pf(expf(-fabsf(x)));
                aux += sp - (e == best ? x : 0.f);
            }
        }
        aux *= (1.f / (Bn * En));
        int nxt = 0;
        for (int e = 1; e < En; ++e)
            if (counts[e] > counts[nxt]) nxt = e;
        out[0] = aux;
        if (out_size > 1) out[1] = (float)nxt;
    }
}

// ---------------------------------------------------------------------------
extern "C" void kernel_launch(void* const* d_in, const int* in_sizes, int n_in,
                              void* d_out, int out_size) {
    const float* hs    = (const float*)d_in[0];
    const float* gamma = (const float*)d_in[1];
    const float* beta  = (const float*)d_in[2];
    const float* w1    = (const float*)d_in[3];
    const float* b1    = (const float*)d_in[4];
    const float* w2    = (const float*)d_in[5];
    const float* b2    = (const float*)d_in[6];
    const float* wr    = (const float*)d_in[7];
    const float* br    = (const float*)d_in[8];

    cudaFuncSetAttribute(gemm_kernel, cudaFuncAttributeMaxDynamicSharedMemorySize, SMEM_BYTES);

    prep_kernel<<<(Dn * Rn + 255) / 256, 256>>>(w1, b2);  // idx 0
    ln_kernel<<<Mn / 8, 256>>>(hs, gamma, beta);           // idx 1
    nop_kernel<<<1, 32>>>();                                // idx 2
    gemm_kernel<<<dim3(Rn / BN, Mn / BM), 256, SMEM_BYTES>>>(b1);  // idx 3 (profiled)
    tail_kernel<<<dim3(8, Bn, 4), 256>>>(w2);
    final_kernel<<<1, 64>>>(wr, br, (float*)d_out, out_size);
}

// round 12
// speedup vs baseline: 1.0335x; 1.0198x over previous
#include <cuda_runtime.h>
#include <cuda_fp16.h>
#include <cstdint>

// Problem constants
constexpr int Bn = 8, Sn = 2048, Dn = 2048, Rn = 512, En = 8;
constexpr int Mn = Bn * Sn;  // 16384 tokens

// Scratch (device globals: allocation-free rule)
__device__ __align__(1024) __half g_xh[(size_t)Mn * Dn];   // 64 MB LN'd acts, fp16
__device__ __align__(1024) __half g_w1h[(size_t)Dn * Rn];  // 2 MB w1 fp16 [D,R]
__device__ float g_H[Bn * Rn];   // per-batch sum of GELU outputs
__device__ float g_T[Bn * Rn];   // per-batch T = H@w2 + S*b2 (seeded)

// ---------------------------------------------------------------------------
__device__ __forceinline__ void cp_async16(uint32_t smem_dst, const void* gmem_src) {
    asm volatile("cp.async.cg.shared.global [%0], [%1], 16;\n" :: "r"(smem_dst), "l"(gmem_src));
}
#define CP_COMMIT() asm volatile("cp.async.commit_group;\n" ::)

__device__ __forceinline__ float gelu_exact(float x) {
    return 0.5f * x * (1.f + erff(x * 0.7071067811865475f));
}

// fp16-accumulate HMMA: D(f16x2 pair) = A*B + C
__device__ __forceinline__ void mma16816_f16(uint32_t* c, const uint32_t* a,
                                             uint32_t b0, uint32_t b1) {
    asm volatile(
        "mma.sync.aligned.m16n8k16.row.col.f16.f16.f16.f16 "
        "{%0,%1}, {%2,%3,%4,%5}, {%6,%7}, {%0,%1};"
        : "+r"(c[0]), "+r"(c[1])
        : "r"(a[0]), "r"(a[1]), "r"(a[2]), "r"(a[3]), "r"(b0), "r"(b1));
}

// ---------------------------------------------------------------------------
// Kernel 1: cast w1 -> fp16 ([D,R] layout), zero H, seed T with S*b2
// ---------------------------------------------------------------------------
__global__ void prep_kernel(const float* __restrict__ w1, const float* __restrict__ b2) {
    int idx = blockIdx.x * blockDim.x + threadIdx.x;
    if (idx < Dn * Rn) g_w1h[idx] = __float2half(w1[idx]);
    if (idx < Bn * Rn) {
        g_H[idx] = 0.f;
        g_T[idx] = (float)Sn * b2[idx & (Rn - 1)];
    }
}

// ---------------------------------------------------------------------------
// Kernel 2: LayerNorm, ONE WARP PER TOKEN (no block barriers), write fp16
// ---------------------------------------------------------------------------
__global__ __launch_bounds__(256) void ln_kernel(const float* __restrict__ hs,
                                                 const float* __restrict__ gamma,
                                                 const float* __restrict__ beta) {
    const int w = threadIdx.x >> 5, l = threadIdx.x & 31;
    const int token = blockIdx.x * 8 + w;
    const float4* row = reinterpret_cast<const float4*>(hs + (size_t)token * Dn);
    const float4* g4 = reinterpret_cast<const float4*>(gamma);
    const float4* b4 = reinterpret_cast<const float4*>(beta);

    float4 v[16];
    float s = 0.f, ss = 0.f;
    #pragma unroll
    for (int i = 0; i < 16; ++i) {
        v[i] = row[l + 32 * i];
        s  += v[i].x + v[i].y + v[i].z + v[i].w;
        ss += v[i].x*v[i].x + v[i].y*v[i].y + v[i].z*v[i].z + v[i].w*v[i].w;
    }
    #pragma unroll
    for (int o = 16; o; o >>= 1) {
        s  += __shfl_xor_sync(0xFFFFFFFFu, s,  o);
        ss += __shfl_xor_sync(0xFFFFFFFFu, ss, o);
    }
    const float mu   = s * (1.f / Dn);
    const float var  = ss * (1.f / Dn) - mu * mu;
    const float rstd = rsqrtf(var + 1e-5f);

    __half2* out2 = reinterpret_cast<__half2*>(g_xh + (size_t)token * Dn);
    #pragma unroll
    for (int i = 0; i < 16; ++i) {
        const int c = l + 32 * i;
        float4 g = g4[c], bb = b4[c];
        out2[2*c]   = __floats2half2_rn((v[i].x-mu)*rstd*g.x+bb.x, (v[i].y-mu)*rstd*g.y+bb.y);
        out2[2*c+1] = __floats2half2_rn((v[i].z-mu)*rstd*g.z+bb.z, (v[i].w-mu)*rstd*g.w+bb.w);
    }
}

// ---------------------------------------------------------------------------
// nop: shifts the ncu capture slot onto the GEMM
// ---------------------------------------------------------------------------
__global__ void nop_kernel() {}

// ---------------------------------------------------------------------------
// Kernel 3: GEMM (xh @ w1h) fp16-acc, f32 promotion every 16 k-iters
//   BM=128 BN=64 BK=32, 256 threads (8 warps, warp tile 32x32), 4-stage ring
//   used as 2 PAIRS: one wait + one barrier per 2 k-iters.
// ---------------------------------------------------------------------------
constexpr int BM = 128, BN = 64, BK = 32;
constexpr int STAGES = 4;
constexpr int ASTR = 40;   // fp16 elems per A row (pad 32->40)
constexpr int BSTR = 72;   // fp16 elems per B row (pad 64->72)
constexpr int A_BUF = BM * ASTR;   // 5120
constexpr int B_BUF = BK * BSTR;   // 2304
constexpr int SMEM_BYTES = STAGES * (A_BUF + B_BUF) * 2;  // 59392

__global__ __launch_bounds__(256) void gemm_kernel(const float* __restrict__ b1) {
    extern __shared__ __align__(1024) unsigned char smem[];
    __half* sA = reinterpret_cast<__half*>(smem);
    __half* sB = sA + STAGES * A_BUF;
    __shared__ float part[4][BN];

    const int tid = threadIdx.x;
    const int bn = blockIdx.x;   // 0..7
    const int bm = blockIdx.y;   // 0..127
    const int warp = tid >> 5, lane = tid & 31;
    const int wm = warp >> 1, wn = warp & 1;

    const uint32_t asBase = (uint32_t)__cvta_generic_to_shared(sA);
    const uint32_t bsBase = (uint32_t)__cvta_generic_to_shared(sB);

    float facc[2][4][4];     // fp32 shadow accumulators
    uint32_t hacc[2][4][2];  // fp16 running accumulators
    #pragma unroll
    for (int i = 0; i < 2; ++i)
        #pragma unroll
        for (int j = 0; j < 4; ++j) {
            #pragma unroll
            for (int k = 0; k < 4; ++k) facc[i][j][k] = 0.f;
            hacc[i][j][0] = 0u; hacc[i][j][1] = 0u;
        }

    const int a_r = tid >> 2, a_c = (tid & 3) * 8;
    const int b_r = tid >> 3, b_c = (tid & 7) * 8;
    const __half* gA0 = g_xh + (size_t)(bm * BM + a_r) * Dn + a_c;
    const __half* gA1 = gA0 + (size_t)64 * Dn;
    const __half* gB0 = g_w1h + (size_t)b_r * Rn + bn * BN + b_c;

    const uint32_t adst0 = asBase + 2u * (uint32_t)(a_r * ASTR + a_c);
    const uint32_t adst1 = asBase + 2u * (uint32_t)((a_r + 64) * ASTR + a_c);
    const uint32_t bdst0 = bsBase + 2u * (uint32_t)(b_r * BSTR + b_c);

    uint32_t abase[2], bbase[2];
    #pragma unroll
    for (int im = 0; im < 2; ++im)
        abase[im] = asBase + 2u * (uint32_t)((wm * 32 + im * 16 + (lane & 15)) * ASTR
                                             + ((lane >> 4) << 3));
    #pragma unroll
    for (int jn = 0; jn < 2; ++jn)
        bbase[jn] = bsBase + 2u * (uint32_t)((lane & 15) * BSTR
                                             + wn * 32 + jn * 16 + ((lane >> 4) << 3));

    constexpr int KT = Dn / BK;    // 64 k-iters
    constexpr int NPAIR = KT / 2;  // 32 pairs

    auto load_stage = [&](int kt, int stg) {
        const int k0 = kt * BK;
        const uint32_t ao = 2u * (uint32_t)(stg * A_BUF);
        const uint32_t bo = 2u * (uint32_t)(stg * B_BUF);
        cp_async16(adst0 + ao, gA0 + k0);
        cp_async16(adst1 + ao, gA1 + k0);
        cp_async16(bdst0 + bo, gB0 + (size_t)k0 * Rn);
    };

    // compute one k-iter from stage stg (immediate)
    auto compute_iter = [&](int stg) {
        const uint32_t aoff0 = 2u * (uint32_t)(stg * A_BUF);
        const uint32_t aoff1 = 2u * (uint32_t)(stg * A_BUF + 16);
        const uint32_t boff0 = 2u * (uint32_t)(stg * B_BUF);
        const uint32_t boff1 = 2u * (uint32_t)(stg * B_BUF + 16 * BSTR);

        uint32_t ra[2][2][4];  // [ks][im]
        #pragma unroll
        for (int im = 0; im < 2; ++im)
            asm volatile("ldmatrix.sync.aligned.m8n8.x4.shared.b16 {%0,%1,%2,%3}, [%4];"
                : "=r"(ra[0][im][0]), "=r"(ra[0][im][1]), "=r"(ra[0][im][2]), "=r"(ra[0][im][3])
                : "r"(abase[im] + aoff0));
        #pragma unroll
        for (int im = 0; im < 2; ++im)
            asm volatile("ldmatrix.sync.aligned.m8n8.x4.shared.b16 {%0,%1,%2,%3}, [%4];"
                : "=r"(ra[1][im][0]), "=r"(ra[1][im][1]), "=r"(ra[1][im][2]), "=r"(ra[1][im][3])
                : "r"(abase[im] + aoff1));

        uint32_t rb[2][4];
        #pragma unroll
        for (int jn = 0; jn < 2; ++jn)
            asm volatile("ldmatrix.sync.aligned.m8n8.x4.trans.shared.b16 {%0,%1,%2,%3}, [%4];"
                : "=r"(rb[jn][0]), "=r"(rb[jn][1]), "=r"(rb[jn][2]), "=r"(rb[jn][3])
                : "r"(bbase[jn] + boff0));
        #pragma unroll
        for (int im = 0; im < 2; ++im)
            #pragma unroll
            for (int jn = 0; jn < 2; ++jn) {
                mma16816_f16(hacc[im][jn * 2 + 0], ra[0][im], rb[jn][0], rb[jn][1]);
                mma16816_f16(hacc[im][jn * 2 + 1], ra[0][im], rb[jn][2], rb[jn][3]);
            }

        #pragma unroll
        for (int jn = 0; jn < 2; ++jn)
            asm volatile("ldmatrix.sync.aligned.m8n8.x4.trans.shared.b16 {%0,%1,%2,%3}, [%4];"
                : "=r"(rb[jn][0]), "=r"(rb[jn][1]), "=r"(rb[jn][2]), "=r"(rb[jn][3])
                : "r"(bbase[jn] + boff1));
        #pragma unroll
        for (int im = 0; im < 2; ++im)
            #pragma unroll
            for (int jn = 0; jn < 2; ++jn) {
                mma16816_f16(hacc[im][jn * 2 + 0], ra[1][im], rb[jn][0], rb[jn][1]);
                mma16816_f16(hacc[im][jn * 2 + 1], ra[1][im], rb[jn][2], rb[jn][3]);
            }
    };

    // prologue: pair 0 (iters 0,1 -> stages 0,1)
    load_stage(0, 0);
    load_stage(1, 1);
    CP_COMMIT();

    for (int pp = 0; pp < NPAIR; pp += 8) {   // promotion window = 8 pairs = 16 iters
        #pragma unroll
        for (int pi = 0; pi < 8; ++pi) {
            const int p = pp + pi;
            const int s0 = (pi & 1) * 2;      // pair parity -> stages {0,1} or {2,3}
            // all outstanding loads (exactly pair p, issued one pair-compute ago) done
            asm volatile("cp.async.wait_group 0;\n" ::);
            // all warps finished computing pair p-1 -> safe to refill its stages
            __syncthreads();
            if (p + 1 < NPAIR) {
                load_stage(2 * (p + 1),     s0 ^ 2);
                load_stage(2 * (p + 1) + 1, (s0 ^ 2) + 1);
            }
            CP_COMMIT();
            compute_iter(s0);
            compute_iter(s0 + 1);
        }
        // promote fp16 window partials into fp32 shadow, reset fp16 accumulators
        #pragma unroll
        for (int im = 0; im < 2; ++im)
            #pragma unroll
            for (int j = 0; j < 4; ++j) {
                float2 lo = __half22float2(*reinterpret_cast<__half2*>(&hacc[im][j][0]));
                float2 hi = __half22float2(*reinterpret_cast<__half2*>(&hacc[im][j][1]));
                facc[im][j][0] += lo.x; facc[im][j][1] += lo.y;
                facc[im][j][2] += hi.x; facc[im][j][3] += hi.y;
                hacc[im][j][0] = 0u; hacc[im][j][1] = 0u;
            }
    }
    __syncthreads();

    // Epilogue: bias + GELU + warp-level column sums
    const int tq = lane & 3;
    const int batch = bm >> 4;
    #pragma unroll
    for (int j = 0; j < 4; ++j) {
        const int gc = bn * BN + wn * 32 + j * 8 + tq * 2;
        const float bi0 = __ldg(b1 + gc), bi1 = __ldg(b1 + gc + 1);
        float s0 = 0.f, s1 = 0.f;
        #pragma unroll
        for (int im = 0; im < 2; ++im) {
            s0 += gelu_exact(facc[im][j][0] + bi0) + gelu_exact(facc[im][j][2] + bi0);
            s1 += gelu_exact(facc[im][j][1] + bi1) + gelu_exact(facc[im][j][3] + bi1);
        }
        #pragma unroll
        for (int o = 4; o <= 16; o <<= 1) {
            s0 += __shfl_xor_sync(0xFFFFFFFFu, s0, o);
            s1 += __shfl_xor_sync(0xFFFFFFFFu, s1, o);
        }
        if (lane < 4) {
            part[wm][wn * 32 + j * 8 + lane * 2]     = s0;
            part[wm][wn * 32 + j * 8 + lane * 2 + 1] = s1;
        }
    }
    __syncthreads();
    if (tid < BN) {
        float s = part[0][tid] + part[1][tid] + part[2][tid] + part[3][tid];
        atomicAdd(&g_H[batch * Rn + bn * BN + tid], s);
    }
}

// ---------------------------------------------------------------------------
// Kernel 4: T += H @ w2  (K-split)  grid (col8, batch8, kseg4) x 256 threads
// ---------------------------------------------------------------------------
__global__ void tail_kernel(const float* __restrict__ w2) {
    __shared__ float sH[128];
    __shared__ float part[4][64];
    const int b  = blockIdx.y;
    const int c0 = blockIdx.x * 64;
    const int k0 = blockIdx.z * 128;
    const int tid = threadIdx.x;
    if (tid < 128) sH[tid] = g_H[b * Rn + k0 + tid];
    __syncthreads();
    const int col = tid & 63, ks = tid >> 6;
    float a = 0.f;
    const float* w2p = w2 + (size_t)(k0 + ks * 32) * Rn + c0 + col;
    #pragma unroll 8
    for (int r = 0; r < 32; ++r)
        a = fmaf(sH[ks * 32 + r], w2p[(size_t)r * Rn], a);
    part[ks][col] = a;
    __syncthreads();
    if (tid < 64) {
        float t = part[0][tid] + part[1][tid] + part[2][tid] + part[3][tid];
        atomicAdd(&g_T[b * Rn + c0 + tid], t);
    }
}

// ---------------------------------------------------------------------------
// Kernel 5: logits = T @ wr + br ; aux loss + mode
// ---------------------------------------------------------------------------
__global__ void final_kernel(const float* __restrict__ wr, const float* __restrict__ br,
                             float* out, int out_size) {
    __shared__ float sl[64];
    const int t = threadIdx.x;
    if (t < 64) {
        const int b = t >> 3, e = t & 7;
        float lg = br[e];
        #pragma unroll 8
        for (int q = 0; q < Rn; ++q) lg = fmaf(g_T[b * Rn + q], wr[q * En + e], lg);
        sl[t] = lg;
    }
    __syncthreads();
    if (t == 0) {
        float aux = 0.f;
        int counts[En] = {};
        for (int b = 0; b < Bn; ++b) {
            const float* l = &sl[b * En];
            int best = 0;
            for (int e = 1; e < En; ++e)
                if (l[e] > l[best]) best = e;
            counts[best]++;
            for (int e = 0; e < En; ++e) {
                float x = l[e];
                float sp = fmaxf(x, 0.f) + log1pf(expf(-fabsf(x)));
                aux += sp - (e == best ? x : 0.f);
            }
        }
        aux *= (1.f / (Bn * En));
        int nxt = 0;
        for (int e = 1; e < En; ++e)
            if (counts[e] > counts[nxt]) nxt = e;
        out[0] = aux;
        if (out_size > 1) out[1] = (float)nxt;
    }
}

// ---------------------------------------------------------------------------
extern "C" void kernel_launch(void* const* d_in, const int* in_sizes, int n_in,
                              void* d_out, int out_size) {
    const float* hs    = (const float*)d_in[0];
    const float* gamma = (const float*)d_in[1];
    const float* beta  = (const float*)d_in[2];
    const float* w1    = (const float*)d_in[3];
    const float* b1    = (const float*)d_in[4];
    const float* w2    = (const float*)d_in[5];
    const float* b2    = (const float*)d_in[6];
    const float* wr    = (const float*)d_in[7];
    const float* br    = (const float*)d_in[8];

    cudaFuncSetAttribute(gemm_kernel, cudaFuncAttributeMaxDynamicSharedMemorySize, SMEM_BYTES);

    prep_kernel<<<(Dn * Rn + 255) / 256, 256>>>(w1, b2);  // idx 0
    ln_kernel<<<Mn / 8, 256>>>(hs, gamma, beta);           // idx 1
    nop_kernel<<<1, 32>>>();                                // idx 2
    gemm_kernel<<<dim3(Rn / BN, Mn / BM), 256, SMEM_BYTES>>>(b1);  // idx 3 (profiled)
    tail_kernel<<<dim3(8, Bn, 4), 256>>>(w2);
    final_kernel<<<1, 64>>>(wr, br, (float*)d_out, out_size);
}

// round 14
// speedup vs baseline: 1.0866x; 1.0514x over previous
#include <cuda_runtime.h>
#include <cuda_fp16.h>
#include <cstdint>

// Problem constants
constexpr int Bn = 8, Sn = 2048, Dn = 2048, Rn = 512, En = 8;
constexpr int Mn = Bn * Sn;  // 16384 tokens

// Scratch (device globals: allocation-free rule)
__device__ __align__(1024) __half g_xh[(size_t)Mn * Dn];   // 64 MB LN'd acts, fp16
__device__ __align__(1024) __half g_w1h[(size_t)Dn * Rn];  // 2 MB w1 fp16 [D,R]
__device__ float g_H[Bn * Rn];   // per-batch sum of GELU outputs
__device__ float g_T[Bn * Rn];   // per-batch T = H@w2 + S*b2 (seeded)

// ---------------------------------------------------------------------------
__device__ __forceinline__ void cp_async16(uint32_t smem_dst, const void* gmem_src) {
    asm volatile("cp.async.cg.shared.global [%0], [%1], 16;\n" :: "r"(smem_dst), "l"(gmem_src));
}
#define CP_COMMIT() asm volatile("cp.async.commit_group;\n" ::)

__device__ __forceinline__ float gelu_exact(float x) {
    return 0.5f * x * (1.f + erff(x * 0.7071067811865475f));
}

// fp16-accumulate HMMA: D(f16x2 pair) = A*B + C
__device__ __forceinline__ void mma16816_f16(uint32_t* c, const uint32_t* a,
                                             uint32_t b0, uint32_t b1) {
    asm volatile(
        "mma.sync.aligned.m16n8k16.row.col.f16.f16.f16.f16 "
        "{%0,%1}, {%2,%3,%4,%5}, {%6,%7}, {%0,%1};"
        : "+r"(c[0]), "+r"(c[1])
        : "r"(a[0]), "r"(a[1]), "r"(a[2]), "r"(a[3]), "r"(b0), "r"(b1));
}

// ---------------------------------------------------------------------------
// Kernel 1 (fused): LayerNorm (one warp per token) + w1 cast + H/T init
//   grid = 2048 blocks x 256 threads (8 tokens per block)
//   each block additionally casts 512 w1 elems; blocks 0..15 init H and T.
// ---------------------------------------------------------------------------
__global__ __launch_bounds__(256) void ln_fused_kernel(const float* __restrict__ hs,
                                                       const float* __restrict__ gamma,
                                                       const float* __restrict__ beta,
                                                       const float* __restrict__ w1,
                                                       const float* __restrict__ b2) {
    // --- side work: w1 cast (2 elems/thread via float2) ---
    {
        const int base = blockIdx.x * 512 + threadIdx.x * 2;
        float2 wv = *reinterpret_cast<const float2*>(w1 + base);
        *reinterpret_cast<__half2*>(g_w1h + base) = __floats2half2_rn(wv.x, wv.y);
    }
    // --- side work: H zero + T seed (blocks 0..15) ---
    if (blockIdx.x < 16) {
        const int idx = blockIdx.x * 256 + threadIdx.x;  // < 4096 = Bn*Rn
        g_H[idx] = 0.f;
        g_T[idx] = (float)Sn * b2[idx & (Rn - 1)];
    }

    // --- LayerNorm: one warp per token ---
    const int w = threadIdx.x >> 5, l = threadIdx.x & 31;
    const int token = blockIdx.x * 8 + w;
    const float4* row = reinterpret_cast<const float4*>(hs + (size_t)token * Dn);
    const float4* g4 = reinterpret_cast<const float4*>(gamma);
    const float4* b4 = reinterpret_cast<const float4*>(beta);

    float4 v[16];
    float s = 0.f, ss = 0.f;
    #pragma unroll
    for (int i = 0; i < 16; ++i) {
        v[i] = row[l + 32 * i];
        s  += v[i].x + v[i].y + v[i].z + v[i].w;
        ss += v[i].x*v[i].x + v[i].y*v[i].y + v[i].z*v[i].z + v[i].w*v[i].w;
    }
    #pragma unroll
    for (int o = 16; o; o >>= 1) {
        s  += __shfl_xor_sync(0xFFFFFFFFu, s,  o);
        ss += __shfl_xor_sync(0xFFFFFFFFu, ss, o);
    }
    const float mu   = s * (1.f / Dn);
    const float var  = ss * (1.f / Dn) - mu * mu;
    const float rstd = rsqrtf(var + 1e-5f);

    __half2* out2 = reinterpret_cast<__half2*>(g_xh + (size_t)token * Dn);
    #pragma unroll
    for (int i = 0; i < 16; ++i) {
        const int c = l + 32 * i;
        float4 g = g4[c], bb = b4[c];
        out2[2*c]   = __floats2half2_rn((v[i].x-mu)*rstd*g.x+bb.x, (v[i].y-mu)*rstd*g.y+bb.y);
        out2[2*c+1] = __floats2half2_rn((v[i].z-mu)*rstd*g.z+bb.z, (v[i].w-mu)*rstd*g.w+bb.w);
    }
}

// ---------------------------------------------------------------------------
// Kernel 2: GEMM (xh @ w1h) fp16-acc, f32 promotion every 8 k-iters (R9 exact)
//   BM=128 BN=64 BK=32, 256 threads (8 warps, warp tile 32x32), 4-stage pipe,
//   one sync per iter, fragment prefetch. Epilogue: +b1, GELU, column reduce.
// ---------------------------------------------------------------------------
constexpr int BM = 128, BN = 64, BK = 32;
constexpr int STAGES = 4;
constexpr int ASTR = 40;   // fp16 elems per A row (pad 32->40)
constexpr int BSTR = 72;   // fp16 elems per B row (pad 64->72)
constexpr int A_BUF = BM * ASTR;   // 5120
constexpr int B_BUF = BK * BSTR;   // 2304
constexpr int SMEM_BYTES = STAGES * (A_BUF + B_BUF) * 2;  // 59392

__global__ __launch_bounds__(256) void gemm_kernel(const float* __restrict__ b1) {
    extern __shared__ __align__(1024) unsigned char smem[];
    __half* sA = reinterpret_cast<__half*>(smem);
    __half* sB = sA + STAGES * A_BUF;
    __shared__ float part[4][BN];

    const int tid = threadIdx.x;
    const int bn = blockIdx.x;   // 0..7
    const int bm = blockIdx.y;   // 0..127
    const int warp = tid >> 5, lane = tid & 31;
    const int wm = warp >> 1, wn = warp & 1;

    const uint32_t asBase = (uint32_t)__cvta_generic_to_shared(sA);
    const uint32_t bsBase = (uint32_t)__cvta_generic_to_shared(sB);

    float facc[2][4][4];     // fp32 shadow accumulators
    uint32_t hacc[2][4][2];  // fp16 running accumulators (f16x2 pairs)
    #pragma unroll
    for (int i = 0; i < 2; ++i)
        #pragma unroll
        for (int j = 0; j < 4; ++j) {
            #pragma unroll
            for (int k = 0; k < 4; ++k) facc[i][j][k] = 0.f;
            hacc[i][j][0] = 0u; hacc[i][j][1] = 0u;
        }

    const int a_r = tid >> 2, a_c = (tid & 3) * 8;
    const int b_r = tid >> 3, b_c = (tid & 7) * 8;
    const __half* gA0 = g_xh + (size_t)(bm * BM + a_r) * Dn + a_c;
    const __half* gA1 = gA0 + (size_t)64 * Dn;
    const __half* gB0 = g_w1h + (size_t)b_r * Rn + bn * BN + b_c;

    const uint32_t adst0 = asBase + 2u * (uint32_t)(a_r * ASTR + a_c);
    const uint32_t adst1 = asBase + 2u * (uint32_t)((a_r + 64) * ASTR + a_c);
    const uint32_t bdst0 = bsBase + 2u * (uint32_t)(b_r * BSTR + b_c);

    uint32_t abase[2], bbase[2];
    #pragma unroll
    for (int im = 0; im < 2; ++im)
        abase[im] = asBase + 2u * (uint32_t)((wm * 32 + im * 16 + (lane & 15)) * ASTR
                                             + ((lane >> 4) << 3));
    #pragma unroll
    for (int jn = 0; jn < 2; ++jn)
        bbase[jn] = bsBase + 2u * (uint32_t)((lane & 15) * BSTR
                                             + wn * 32 + jn * 16 + ((lane >> 4) << 3));

    constexpr int KT = Dn / BK;  // 64

    auto load_stage = [&](int kt, int stg) {
        const int k0 = kt * BK;
        const uint32_t ao = 2u * (uint32_t)(stg * A_BUF);
        const uint32_t bo = 2u * (uint32_t)(stg * B_BUF);
        cp_async16(adst0 + ao, gA0 + k0);
        cp_async16(adst1 + ao, gA1 + k0);
        cp_async16(bdst0 + bo, gB0 + (size_t)k0 * Rn);
    };

    load_stage(0, 0); CP_COMMIT();
    load_stage(1, 1); CP_COMMIT();
    load_stage(2, 2); CP_COMMIT();

    for (int kt0 = 0; kt0 < KT; kt0 += 8) {
        #pragma unroll
        for (int si = 0; si < 8; ++si) {
            const int kt = kt0 + si;
            const int s = kt & 3;
            asm volatile("cp.async.wait_group 2;\n" ::);
            __syncthreads();
            if (kt + 3 < KT) load_stage(kt + 3, (kt + 3) & 3);
            CP_COMMIT();

            const uint32_t aoff0 = 2u * (uint32_t)(s * A_BUF);
            const uint32_t aoff1 = 2u * (uint32_t)(s * A_BUF + 16);
            const uint32_t boff0 = 2u * (uint32_t)(s * B_BUF);
            const uint32_t boff1 = 2u * (uint32_t)(s * B_BUF + 16 * BSTR);

            uint32_t ra[2][2][4];  // [ks][im]
            #pragma unroll
            for (int im = 0; im < 2; ++im)
                asm volatile("ldmatrix.sync.aligned.m8n8.x4.shared.b16 {%0,%1,%2,%3}, [%4];"
                    : "=r"(ra[0][im][0]), "=r"(ra[0][im][1]), "=r"(ra[0][im][2]), "=r"(ra[0][im][3])
                    : "r"(abase[im] + aoff0));
            #pragma unroll
            for (int im = 0; im < 2; ++im)
                asm volatile("ldmatrix.sync.aligned.m8n8.x4.shared.b16 {%0,%1,%2,%3}, [%4];"
                    : "=r"(ra[1][im][0]), "=r"(ra[1][im][1]), "=r"(ra[1][im][2]), "=r"(ra[1][im][3])
                    : "r"(abase[im] + aoff1));

            uint32_t rb[2][4];
            #pragma unroll
            for (int jn = 0; jn < 2; ++jn)
                asm volatile("ldmatrix.sync.aligned.m8n8.x4.trans.shared.b16 {%0,%1,%2,%3}, [%4];"
                    : "=r"(rb[jn][0]), "=r"(rb[jn][1]), "=r"(rb[jn][2]), "=r"(rb[jn][3])
                    : "r"(bbase[jn] + boff0));
            #pragma unroll
            for (int im = 0; im < 2; ++im)
                #pragma unroll
                for (int jn = 0; jn < 2; ++jn) {
                    mma16816_f16(hacc[im][jn * 2 + 0], ra[0][im], rb[jn][0], rb[jn][1]);
                    mma16816_f16(hacc[im][jn * 2 + 1], ra[0][im], rb[jn][2], rb[jn][3]);
                }

            #pragma unroll
            for (int jn = 0; jn < 2; ++jn)
                asm volatile("ldmatrix.sync.aligned.m8n8.x4.trans.shared.b16 {%0,%1,%2,%3}, [%4];"
                    : "=r"(rb[jn][0]), "=r"(rb[jn][1]), "=r"(rb[jn][2]), "=r"(rb[jn][3])
                    : "r"(bbase[jn] + boff1));
            #pragma unroll
            for (int im = 0; im < 2; ++im)
                #pragma unroll
                for (int jn = 0; jn < 2; ++jn) {
                    mma16816_f16(hacc[im][jn * 2 + 0], ra[1][im], rb[jn][0], rb[jn][1]);
                    mma16816_f16(hacc[im][jn * 2 + 1], ra[1][im], rb[jn][2], rb[jn][3]);
                }
        }
        // promote fp16 window partials into fp32 shadow, reset fp16 accumulators
        #pragma unroll
        for (int im = 0; im < 2; ++im)
            #pragma unroll
            for (int j = 0; j < 4; ++j) {
                float2 lo = __half22float2(*reinterpret_cast<__half2*>(&hacc[im][j][0]));
                float2 hi = __half22float2(*reinterpret_cast<__half2*>(&hacc[im][j][1]));
                facc[im][j][0] += lo.x; facc[im][j][1] += lo.y;
                facc[im][j][2] += hi.x; facc[im][j][3] += hi.y;
                hacc[im][j][0] = 0u; hacc[im][j][1] = 0u;
            }
    }
    __syncthreads();

    // Epilogue: bias + GELU + warp-level column sums
    const int tq = lane & 3;
    const int batch = bm >> 4;
    #pragma unroll
    for (int j = 0; j < 4; ++j) {
        const int gc = bn * BN + wn * 32 + j * 8 + tq * 2;
        const float bi0 = __ldg(b1 + gc), bi1 = __ldg(b1 + gc + 1);
        float s0 = 0.f, s1 = 0.f;
        #pragma unroll
        for (int im = 0; im < 2; ++im) {
            s0 += gelu_exact(facc[im][j][0] + bi0) + gelu_exact(facc[im][j][2] + bi0);
            s1 += gelu_exact(facc[im][j][1] + bi1) + gelu_exact(facc[im][j][3] + bi1);
        }
        #pragma unroll
        for (int o = 4; o <= 16; o <<= 1) {
            s0 += __shfl_xor_sync(0xFFFFFFFFu, s0, o);
            s1 += __shfl_xor_sync(0xFFFFFFFFu, s1, o);
        }
        if (lane < 4) {
            part[wm][wn * 32 + j * 8 + lane * 2]     = s0;
            part[wm][wn * 32 + j * 8 + lane * 2 + 1] = s1;
        }
    }
    __syncthreads();
    if (tid < BN) {
        float s = part[0][tid] + part[1][tid] + part[2][tid] + part[3][tid];
        atomicAdd(&g_H[batch * Rn + bn * BN + tid], s);
    }
}

// ---------------------------------------------------------------------------
// Kernel 3: T += H @ w2  (K-split)  grid (col8, batch8, kseg4) x 256 threads
// ---------------------------------------------------------------------------
__global__ void tail_kernel(const float* __restrict__ w2) {
    __shared__ float sH[128];
    __shared__ float part[4][64];
    const int b  = blockIdx.y;
    const int c0 = blockIdx.x * 64;
    const int k0 = blockIdx.z * 128;
    const int tid = threadIdx.x;
    if (tid < 128) sH[tid] = g_H[b * Rn + k0 + tid];
    __syncthreads();
    const int col = tid & 63, ks = tid >> 6;
    float a = 0.f;
    const float* w2p = w2 + (size_t)(k0 + ks * 32) * Rn + c0 + col;
    #pragma unroll 8
    for (int r = 0; r < 32; ++r)
        a = fmaf(sH[ks * 32 + r], w2p[(size_t)r * Rn], a);
    part[ks][col] = a;
    __syncthreads();
    if (tid < 64) {
        float t = part[0][tid] + part[1][tid] + part[2][tid] + part[3][tid];
        atomicAdd(&g_T[b * Rn + c0 + tid], t);
    }
}

// ---------------------------------------------------------------------------
// Kernel 4: logits = T @ wr + br ; aux loss + mode
// ---------------------------------------------------------------------------
__global__ void final_kernel(const float* __restrict__ wr, const float* __restrict__ br,
                             float* out, int out_size) {
    __shared__ float sl[64];
    const int t = threadIdx.x;
    if (t < 64) {
        const int b = t >> 3, e = t & 7;
        float lg = br[e];
        #pragma unroll 8
        for (int q = 0; q < Rn; ++q) lg = fmaf(g_T[b * Rn + q], wr[q * En + e], lg);
        sl[t] = lg;
    }
    __syncthreads();
    if (t == 0) {
        float aux = 0.f;
        int counts[En] = {};
        for (int b = 0; b < Bn; ++b) {
            const float* l = &sl[b * En];
            int best = 0;
            for (int e = 1; e < En; ++e)
                if (l[e] > l[best]) best = e;
            counts[best]++;
            for (int e = 0; e < En; ++e) {
                float x = l[e];
                float sp = fmaxf(x, 0.f) + log1pf(expf(-fabsf(x)));
                aux += sp - (e == best ? x : 0.f);
            }
        }
        aux *= (1.f / (Bn * En));
        int nxt = 0;
        for (int e = 1; e < En; ++e)
            if (counts[e] > counts[nxt]) nxt = e;
        out[0] = aux;
        if (out_size > 1) out[1] = (float)nxt;
    }
}

// ---------------------------------------------------------------------------
extern "C" void kernel_launch(void* const* d_in, const int* in_sizes, int n_in,
                              void* d_out, int out_size) {
    const float* hs    = (const float*)d_in[0];
    const float* gamma = (const float*)d_in[1];
    const float* beta  = (const float*)d_in[2];
    const float* w1    = (const float*)d_in[3];
    const float* b1    = (const float*)d_in[4];
    const float* w2    = (const float*)d_in[5];
    const float* b2    = (const float*)d_in[6];
    const float* wr    = (const float*)d_in[7];
    const float* br    = (const float*)d_in[8];

    cudaFuncSetAttribute(gemm_kernel, cudaFuncAttributeMaxDynamicSharedMemorySize, SMEM_BYTES);

    ln_fused_kernel<<<Mn / 8, 256>>>(hs, gamma, beta, w1, b2);     // idx 0
    gemm_kernel<<<dim3(Rn / BN, Mn / BM), 256, SMEM_BYTES>>>(b1);  // idx 1
    tail_kernel<<<dim3(8, Bn, 4), 256>>>(w2);                      // idx 2
    final_kernel<<<1, 64>>>(wr, br, (float*)d_out, out_size);      // idx 3
}

// round 16
// speedup vs baseline: 1.2337x; 1.1354x over previous
#include <cuda_runtime.h>
#include <cuda_fp16.h>
#include <cstdint>

// Problem constants
constexpr int Bn = 8, Sn = 2048, Dn = 2048, Rn = 512, En = 8;
constexpr int Mn = Bn * Sn;  // 16384 tokens

// Scratch (device globals: allocation-free rule)
__device__ __align__(1024) __half g_xh[(size_t)Mn * Dn];   // 64 MB LN'd acts, fp16
__device__ __align__(1024) __half g_w1h[(size_t)Dn * Rn];  // 2 MB w1 fp16 [D,R]
__device__ float g_H[Bn * Rn];   // per-batch sum of GELU outputs
__device__ float g_T[Bn * Rn];   // per-batch T = H@w2 + S*b2 (seeded)

// ---------------------------------------------------------------------------
__device__ __forceinline__ void cp_async16(uint32_t smem_dst, const void* gmem_src) {
    asm volatile("cp.async.cg.shared.global [%0], [%1], 16;\n" :: "r"(smem_dst), "l"(gmem_src));
}
#define CP_COMMIT() asm volatile("cp.async.commit_group;\n" ::)

__device__ __forceinline__ float gelu_exact(float x) {
    return 0.5f * x * (1.f + erff(x * 0.7071067811865475f));
}

// fp16-accumulate HMMA: D(f16x2 pair) = A*B + C
__device__ __forceinline__ void mma16816_f16(uint32_t* c, const uint32_t* a,
                                             uint32_t b0, uint32_t b1) {
    asm volatile(
        "mma.sync.aligned.m16n8k16.row.col.f16.f16.f16.f16 "
        "{%0,%1}, {%2,%3,%4,%5}, {%6,%7}, {%0,%1};"
        : "+r"(c[0]), "+r"(c[1])
        : "r"(a[0]), "r"(a[1]), "r"(a[2]), "r"(a[3]), "r"(b0), "r"(b1));
}

// ---------------------------------------------------------------------------
// Kernel 1 (fused): LayerNorm (one warp per token) + w1 cast + H/T init
// ---------------------------------------------------------------------------
__global__ __launch_bounds__(256) void ln_fused_kernel(const float* __restrict__ hs,
                                                       const float* __restrict__ gamma,
                                                       const float* __restrict__ beta,
                                                       const float* __restrict__ w1,
                                                       const float* __restrict__ b2) {
    // --- side work: w1 cast (2 elems/thread via float2) ---
    {
        const int base = blockIdx.x * 512 + threadIdx.x * 2;
        float2 wv = *reinterpret_cast<const float2*>(w1 + base);
        *reinterpret_cast<__half2*>(g_w1h + base) = __floats2half2_rn(wv.x, wv.y);
    }
    // --- side work: H zero + T seed (blocks 0..15) ---
    if (blockIdx.x < 16) {
        const int idx = blockIdx.x * 256 + threadIdx.x;  // < 4096 = Bn*Rn
        g_H[idx] = 0.f;
        g_T[idx] = (float)Sn * b2[idx & (Rn - 1)];
    }

    // --- LayerNorm: one warp per token ---
    const int w = threadIdx.x >> 5, l = threadIdx.x & 31;
    const int token = blockIdx.x * 8 + w;
    const float4* row = reinterpret_cast<const float4*>(hs + (size_t)token * Dn);
    const float4* g4 = reinterpret_cast<const float4*>(gamma);
    const float4* b4 = reinterpret_cast<const float4*>(beta);

    float4 v[16];
    float s = 0.f, ss = 0.f;
    #pragma unroll
    for (int i = 0; i < 16; ++i) {
        v[i] = row[l + 32 * i];
        s  += v[i].x + v[i].y + v[i].z + v[i].w;
        ss += v[i].x*v[i].x + v[i].y*v[i].y + v[i].z*v[i].z + v[i].w*v[i].w;
    }
    #pragma unroll
    for (int o = 16; o; o >>= 1) {
        s  += __shfl_xor_sync(0xFFFFFFFFu, s,  o);
        ss += __shfl_xor_sync(0xFFFFFFFFu, ss, o);
    }
    const float mu   = s * (1.f / Dn);
    const float var  = ss * (1.f / Dn) - mu * mu;
    const float rstd = rsqrtf(var + 1e-5f);

    __half2* out2 = reinterpret_cast<__half2*>(g_xh + (size_t)token * Dn);
    #pragma unroll
    for (int i = 0; i < 16; ++i) {
        const int c = l + 32 * i;
        float4 g = g4[c], bb = b4[c];
        out2[2*c]   = __floats2half2_rn((v[i].x-mu)*rstd*g.x+bb.x, (v[i].y-mu)*rstd*g.y+bb.y);
        out2[2*c+1] = __floats2half2_rn((v[i].z-mu)*rstd*g.z+bb.z, (v[i].w-mu)*rstd*g.w+bb.w);
    }
}

// ---------------------------------------------------------------------------
// Kernel 2: GEMM (xh @ w1h) fp16-acc, f32 promotion every 8 k-iters (R9 exact)
// ---------------------------------------------------------------------------
constexpr int BM = 128, BN = 64, BK = 32;
constexpr int STAGES = 4;
constexpr int ASTR = 40;   // fp16 elems per A row (pad 32->40)
constexpr int BSTR = 72;   // fp16 elems per B row (pad 64->72)
constexpr int A_BUF = BM * ASTR;   // 5120
constexpr int B_BUF = BK * BSTR;   // 2304
constexpr int SMEM_BYTES = STAGES * (A_BUF + B_BUF) * 2;  // 59392

__global__ __launch_bounds__(256) void gemm_kernel(const float* __restrict__ b1) {
    extern __shared__ __align__(1024) unsigned char smem[];
    __half* sA = reinterpret_cast<__half*>(smem);
    __half* sB = sA + STAGES * A_BUF;
    __shared__ float part[4][BN];

    const int tid = threadIdx.x;
    const int bn = blockIdx.x;   // 0..7
    const int bm = blockIdx.y;   // 0..127
    const int warp = tid >> 5, lane = tid & 31;
    const int wm = warp >> 1, wn = warp & 1;

    const uint32_t asBase = (uint32_t)__cvta_generic_to_shared(sA);
    const uint32_t bsBase = (uint32_t)__cvta_generic_to_shared(sB);

    float facc[2][4][4];     // fp32 shadow accumulators
    uint32_t hacc[2][4][2];  // fp16 running accumulators (f16x2 pairs)
    #pragma unroll
    for (int i = 0; i < 2; ++i)
        #pragma unroll
        for (int j = 0; j < 4; ++j) {
            #pragma unroll
            for (int k = 0; k < 4; ++k) facc[i][j][k] = 0.f;
            hacc[i][j][0] = 0u; hacc[i][j][1] = 0u;
        }

    const int a_r = tid >> 2, a_c = (tid & 3) * 8;
    const int b_r = tid >> 3, b_c = (tid & 7) * 8;
    const __half* gA0 = g_xh + (size_t)(bm * BM + a_r) * Dn + a_c;
    const __half* gA1 = gA0 + (size_t)64 * Dn;
    const __half* gB0 = g_w1h + (size_t)b_r * Rn + bn * BN + b_c;

    const uint32_t adst0 = asBase + 2u * (uint32_t)(a_r * ASTR + a_c);
    const uint32_t adst1 = asBase + 2u * (uint32_t)((a_r + 64) * ASTR + a_c);
    const uint32_t bdst0 = bsBase + 2u * (uint32_t)(b_r * BSTR + b_c);

    uint32_t abase[2], bbase[2];
    #pragma unroll
    for (int im = 0; im < 2; ++im)
        abase[im] = asBase + 2u * (uint32_t)((wm * 32 + im * 16 + (lane & 15)) * ASTR
                                             + ((lane >> 4) << 3));
    #pragma unroll
    for (int jn = 0; jn < 2; ++jn)
        bbase[jn] = bsBase + 2u * (uint32_t)((lane & 15) * BSTR
                                             + wn * 32 + jn * 16 + ((lane >> 4) << 3));

    constexpr int KT = Dn / BK;  // 64

    auto load_stage = [&](int kt, int stg) {
        const int k0 = kt * BK;
        const uint32_t ao = 2u * (uint32_t)(stg * A_BUF);
        const uint32_t bo = 2u * (uint32_t)(stg * B_BUF);
        cp_async16(adst0 + ao, gA0 + k0);
        cp_async16(adst1 + ao, gA1 + k0);
        cp_async16(bdst0 + bo, gB0 + (size_t)k0 * Rn);
    };

    load_stage(0, 0); CP_COMMIT();
    load_stage(1, 1); CP_COMMIT();
    load_stage(2, 2); CP_COMMIT();

    for (int kt0 = 0; kt0 < KT; kt0 += 8) {
        #pragma unroll
        for (int si = 0; si < 8; ++si) {
            const int kt = kt0 + si;
            const int s = kt & 3;
            asm volatile("cp.async.wait_group 2;\n" ::);
            __syncthreads();
            if (kt + 3 < KT) load_stage(kt + 3, (kt + 3) & 3);
            CP_COMMIT();

            const uint32_t aoff0 = 2u * (uint32_t)(s * A_BUF);
            const uint32_t aoff1 = 2u * (uint32_t)(s * A_BUF + 16);
            const uint32_t boff0 = 2u * (uint32_t)(s * B_BUF);
            const uint32_t boff1 = 2u * (uint32_t)(s * B_BUF + 16 * BSTR);

            uint32_t ra[2][2][4];  // [ks][im]
            #pragma unroll
            for (int im = 0; im < 2; ++im)
                asm volatile("ldmatrix.sync.aligned.m8n8.x4.shared.b16 {%0,%1,%2,%3}, [%4];"
                    : "=r"(ra[0][im][0]), "=r"(ra[0][im][1]), "=r"(ra[0][im][2]), "=r"(ra[0][im][3])
                    : "r"(abase[im] + aoff0));
            #pragma unroll
            for (int im = 0; im < 2; ++im)
                asm volatile("ldmatrix.sync.aligned.m8n8.x4.shared.b16 {%0,%1,%2,%3}, [%4];"
                    : "=r"(ra[1][im][0]), "=r"(ra[1][im][1]), "=r"(ra[1][im][2]), "=r"(ra[1][im][3])
                    : "r"(abase[im] + aoff1));

            uint32_t rb[2][4];
            #pragma unroll
            for (int jn = 0; jn < 2; ++jn)
                asm volatile("ldmatrix.sync.aligned.m8n8.x4.trans.shared.b16 {%0,%1,%2,%3}, [%4];"
                    : "=r"(rb[jn][0]), "=r"(rb[jn][1]), "=r"(rb[jn][2]), "=r"(rb[jn][3])
                    : "r"(bbase[jn] + boff0));
            #pragma unroll
            for (int im = 0; im < 2; ++im)
                #pragma unroll
                for (int jn = 0; jn < 2; ++jn) {
                    mma16816_f16(hacc[im][jn * 2 + 0], ra[0][im], rb[jn][0], rb[jn][1]);
                    mma16816_f16(hacc[im][jn * 2 + 1], ra[0][im], rb[jn][2], rb[jn][3]);
                }

            #pragma unroll
            for (int jn = 0; jn < 2; ++jn)
                asm volatile("ldmatrix.sync.aligned.m8n8.x4.trans.shared.b16 {%0,%1,%2,%3}, [%4];"
                    : "=r"(rb[jn][0]), "=r"(rb[jn][1]), "=r"(rb[jn][2]), "=r"(rb[jn][3])
                    : "r"(bbase[jn] + boff1));
            #pragma unroll
            for (int im = 0; im < 2; ++im)
                #pragma unroll
                for (int jn = 0; jn < 2; ++jn) {
                    mma16816_f16(hacc[im][jn * 2 + 0], ra[1][im], rb[jn][0], rb[jn][1]);
                    mma16816_f16(hacc[im][jn * 2 + 1], ra[1][im], rb[jn][2], rb[jn][3]);
                }
        }
        // promote fp16 window partials into fp32 shadow, reset fp16 accumulators
        #pragma unroll
        for (int im = 0; im < 2; ++im)
            #pragma unroll
            for (int j = 0; j < 4; ++j) {
                float2 lo = __half22float2(*reinterpret_cast<__half2*>(&hacc[im][j][0]));
                float2 hi = __half22float2(*reinterpret_cast<__half2*>(&hacc[im][j][1]));
                facc[im][j][0] += lo.x; facc[im][j][1] += lo.y;
                facc[im][j][2] += hi.x; facc[im][j][3] += hi.y;
                hacc[im][j][0] = 0u; hacc[im][j][1] = 0u;
            }
    }
    __syncthreads();

    // Epilogue: bias + GELU + warp-level column sums
    const int tq = lane & 3;
    const int batch = bm >> 4;
    #pragma unroll
    for (int j = 0; j < 4; ++j) {
        const int gc = bn * BN + wn * 32 + j * 8 + tq * 2;
        const float bi0 = __ldg(b1 + gc), bi1 = __ldg(b1 + gc + 1);
        float s0 = 0.f, s1 = 0.f;
        #pragma unroll
        for (int im = 0; im < 2; ++im) {
            s0 += gelu_exact(facc[im][j][0] + bi0) + gelu_exact(facc[im][j][2] + bi0);
            s1 += gelu_exact(facc[im][j][1] + bi1) + gelu_exact(facc[im][j][3] + bi1);
        }
        #pragma unroll
        for (int o = 4; o <= 16; o <<= 1) {
            s0 += __shfl_xor_sync(0xFFFFFFFFu, s0, o);
            s1 += __shfl_xor_sync(0xFFFFFFFFu, s1, o);
        }
        if (lane < 4) {
            part[wm][wn * 32 + j * 8 + lane * 2]     = s0;
            part[wm][wn * 32 + j * 8 + lane * 2 + 1] = s1;
        }
    }
    __syncthreads();
    if (tid < BN) {
        float s = part[0][tid] + part[1][tid] + part[2][tid] + part[3][tid];
        atomicAdd(&g_H[batch * Rn + bn * BN + tid], s);
    }
}

// ---------------------------------------------------------------------------
// Kernel 3: T += H @ w2  (K-split)  grid (col8, batch8, kseg4) x 256 threads
// ---------------------------------------------------------------------------
__global__ void tail_kernel(const float* __restrict__ w2) {
    __shared__ float sH[128];
    __shared__ float part[4][64];
    const int b  = blockIdx.y;
    const int c0 = blockIdx.x * 64;
    const int k0 = blockIdx.z * 128;
    const int tid = threadIdx.x;
    if (tid < 128) sH[tid] = g_H[b * Rn + k0 + tid];
    __syncthreads();
    const int col = tid & 63, ks = tid >> 6;
    float a = 0.f;
    const float* w2p = w2 + (size_t)(k0 + ks * 32) * Rn + c0 + col;
    #pragma unroll 8
    for (int r = 0; r < 32; ++r)
        a = fmaf(sH[ks * 32 + r], w2p[(size_t)r * Rn], a);
    part[ks][col] = a;
    __syncthreads();
    if (tid < 64) {
        float t = part[0][tid] + part[1][tid] + part[2][tid] + part[3][tid];
        atomicAdd(&g_T[b * Rn + c0 + tid], t);
    }
}

// ---------------------------------------------------------------------------
// Kernel 4: logits = T @ wr + br ; aux loss + mode
//   1 block x 512 threads; g_T and wr staged in smem (1024 float4 each ->
//   2 float4 per thread), warp-per-4-pairs shfl reduce.
// ---------------------------------------------------------------------------
__global__ __launch_bounds__(512) void final_kernel(const float* __restrict__ wr,
                                                    const float* __restrict__ br,
                                                    float* out, int out_size) {
    __shared__ float sT[Bn * Rn];   // 4096 floats = 1024 float4
    __shared__ float sW[Rn * En];   // 4096 floats = 1024 float4
    __shared__ float sl[Bn * En];   // 64 logits
    const int tid = threadIdx.x;

    // cooperative stage: 2 float4 per thread from each matrix
    {
        const float4* gT4 = reinterpret_cast<const float4*>(g_T);
        const float4* gW4 = reinterpret_cast<const float4*>(wr);
        float4* sT4 = reinterpret_cast<float4*>(sT);
        float4* sW4 = reinterpret_cast<float4*>(sW);
        #pragma unroll
        for (int i = 0; i < 2; ++i) {          // 512 threads x 2 = 1024 float4
            sT4[tid + 512 * i] = gT4[tid + 512 * i];
            sW4[tid + 512 * i] = gW4[tid + 512 * i];
        }
    }
    __syncthreads();

    // 16 warps x 4 pairs each = 64 (b,e) pairs
    const int w = tid >> 5, l = tid & 31;
    #pragma unroll
    for (int pi = 0; pi < 4; ++pi) {
        const int p = w * 4 + pi;
        const int b = p >> 3, e = p & 7;
        float a = 0.f;
        #pragma unroll
        for (int i = 0; i < 16; ++i) {
            const int q = l + 32 * i;
            a = fmaf(sT[b * Rn + q], sW[q * En + e], a);
        }
        #pragma unroll
        for (int o = 16; o; o >>= 1) a += __shfl_xor_sync(0xFFFFFFFFu, a, o);
        if (l == 0) sl[p] = a + br[e];
    }
    __syncthreads();

    if (tid == 0) {
        float aux = 0.f;
        int counts[En] = {};
        for (int b = 0; b < Bn; ++b) {
            const float* lg = &sl[b * En];
            int best = 0;
            for (int e = 1; e < En; ++e)
                if (lg[e] > lg[best]) best = e;
            counts[best]++;
            for (int e = 0; e < En; ++e) {
                float x = lg[e];
                float sp = fmaxf(x, 0.f) + log1pf(expf(-fabsf(x)));
                aux += sp - (e == best ? x : 0.f);
            }
        }
        aux *= (1.f / (Bn * En));
        int nxt = 0;
        for (int e = 1; e < En; ++e)
            if (counts[e] > counts[nxt]) nxt = e;
        out[0] = aux;
        if (out_size > 1) out[1] = (float)nxt;
    }
}

// ---------------------------------------------------------------------------
extern "C" void kernel_launch(void* const* d_in, const int* in_sizes, int n_in,
                              void* d_out, int out_size) {
    const float* hs    = (const float*)d_in[0];
    const float* gamma = (const float*)d_in[1];
    const float* beta  = (const float*)d_in[2];
    const float* w1    = (const float*)d_in[3];
    const float* b1    = (const float*)d_in[4];
    const float* w2    = (const float*)d_in[5];
    const float* b2    = (const float*)d_in[6];
    const float* wr    = (const float*)d_in[7];
    const float* br    = (const float*)d_in[8];

    cudaFuncSetAttribute(gemm_kernel, cudaFuncAttributeMaxDynamicSharedMemorySize, SMEM_BYTES);

    ln_fused_kernel<<<Mn / 8, 256>>>(hs, gamma, beta, w1, b2);     // idx 0
    gemm_kernel<<<dim3(Rn / BN, Mn / BM), 256, SMEM_BYTES>>>(b1);  // idx 1
    tail_kernel<<<dim3(8, Bn, 4), 256>>>(w2);                      // idx 2
    final_kernel<<<1, 512>>>(wr, br, (float*)d_out, out_size);     // idx 3
}

// round 17
// speedup vs baseline: 1.2378x; 1.0033x over previous
#include <cuda_runtime.h>
#include <cuda_fp16.h>
#include <cstdint>

// Problem constants
constexpr int Bn = 8, Sn = 2048, Dn = 2048, Rn = 512, En = 8;
constexpr int Mn = Bn * Sn;  // 16384 tokens

// Scratch (device globals: allocation-free rule)
__device__ __align__(1024) __half g_xh[(size_t)Mn * Dn];   // 64 MB LN'd acts, fp16
__device__ __align__(1024) __half g_w1h[(size_t)Dn * Rn];  // 2 MB w1 fp16 [D,R]
__device__ float g_H[Bn * Rn];   // per-batch sum of GELU outputs
__device__ float g_T[Bn * Rn];   // per-batch T = H@w2 + S*b2 (seeded)

// ---------------------------------------------------------------------------
__device__ __forceinline__ void cp_async16(uint32_t smem_dst, const void* gmem_src) {
    asm volatile("cp.async.cg.shared.global [%0], [%1], 16;\n" :: "r"(smem_dst), "l"(gmem_src));
}
#define CP_COMMIT() asm volatile("cp.async.commit_group;\n" ::)

__device__ __forceinline__ float gelu_exact(float x) {
    return 0.5f * x * (1.f + erff(x * 0.7071067811865475f));
}

// fp16-accumulate HMMA: D(f16x2 pair) = A*B + C
__device__ __forceinline__ void mma16816_f16(uint32_t* c, const uint32_t* a,
                                             uint32_t b0, uint32_t b1) {
    asm volatile(
        "mma.sync.aligned.m16n8k16.row.col.f16.f16.f16.f16 "
        "{%0,%1}, {%2,%3,%4,%5}, {%6,%7}, {%0,%1};"
        : "+r"(c[0]), "+r"(c[1])
        : "r"(a[0]), "r"(a[1]), "r"(a[2]), "r"(a[3]), "r"(b0), "r"(b1));
}

// ---------------------------------------------------------------------------
// Kernel 1 (fused): LayerNorm (one warp per token) + w1 cast + H/T init
// ---------------------------------------------------------------------------
__global__ __launch_bounds__(256) void ln_fused_kernel(const float* __restrict__ hs,
                                                       const float* __restrict__ gamma,
                                                       const float* __restrict__ beta,
                                                       const float* __restrict__ w1,
                                                       const float* __restrict__ b2) {
    // --- side work: w1 cast (2 elems/thread via float2) ---
    {
        const int base = blockIdx.x * 512 + threadIdx.x * 2;
        float2 wv = *reinterpret_cast<const float2*>(w1 + base);
        *reinterpret_cast<__half2*>(g_w1h + base) = __floats2half2_rn(wv.x, wv.y);
    }
    // --- side work: H zero + T seed (blocks 0..15) ---
    if (blockIdx.x < 16) {
        const int idx = blockIdx.x * 256 + threadIdx.x;  // < 4096 = Bn*Rn
        g_H[idx] = 0.f;
        g_T[idx] = (float)Sn * b2[idx & (Rn - 1)];
    }

    // --- LayerNorm: one warp per token ---
    const int w = threadIdx.x >> 5, l = threadIdx.x & 31;
    const int token = blockIdx.x * 8 + w;
    const float4* row = reinterpret_cast<const float4*>(hs + (size_t)token * Dn);
    const float4* g4 = reinterpret_cast<const float4*>(gamma);
    const float4* b4 = reinterpret_cast<const float4*>(beta);

    float4 v[16];
    float s = 0.f, ss = 0.f;
    #pragma unroll
    for (int i = 0; i < 16; ++i) {
        v[i] = row[l + 32 * i];
        s  += v[i].x + v[i].y + v[i].z + v[i].w;
        ss += v[i].x*v[i].x + v[i].y*v[i].y + v[i].z*v[i].z + v[i].w*v[i].w;
    }
    #pragma unroll
    for (int o = 16; o; o >>= 1) {
        s  += __shfl_xor_sync(0xFFFFFFFFu, s,  o);
        ss += __shfl_xor_sync(0xFFFFFFFFu, ss, o);
    }
    const float mu   = s * (1.f / Dn);
    const float var  = ss * (1.f / Dn) - mu * mu;
    const float rstd = rsqrtf(var + 1e-5f);

    __half2* out2 = reinterpret_cast<__half2*>(g_xh + (size_t)token * Dn);
    #pragma unroll
    for (int i = 0; i < 16; ++i) {
        const int c = l + 32 * i;
        float4 g = g4[c], bb = b4[c];
        out2[2*c]   = __floats2half2_rn((v[i].x-mu)*rstd*g.x+bb.x, (v[i].y-mu)*rstd*g.y+bb.y);
        out2[2*c+1] = __floats2half2_rn((v[i].z-mu)*rstd*g.z+bb.z, (v[i].w-mu)*rstd*g.w+bb.w);
    }
}

// ---------------------------------------------------------------------------
// Kernel 2: GEMM (xh @ w1h) fp16-acc, f32 promotion every 8 k-iters (R9 exact)
// ---------------------------------------------------------------------------
constexpr int BM = 128, BN = 64, BK = 32;
constexpr int STAGES = 4;
constexpr int ASTR = 40;   // fp16 elems per A row (pad 32->40)
constexpr int BSTR = 72;   // fp16 elems per B row (pad 64->72)
constexpr int A_BUF = BM * ASTR;   // 5120
constexpr int B_BUF = BK * BSTR;   // 2304
constexpr int SMEM_BYTES = STAGES * (A_BUF + B_BUF) * 2;  // 59392

__global__ __launch_bounds__(256) void gemm_kernel(const float* __restrict__ b1) {
    extern __shared__ __align__(1024) unsigned char smem[];
    __half* sA = reinterpret_cast<__half*>(smem);
    __half* sB = sA + STAGES * A_BUF;
    __shared__ float part[4][BN];

    const int tid = threadIdx.x;
    const int bn = blockIdx.x;   // 0..7
    const int bm = blockIdx.y;   // 0..127
    const int warp = tid >> 5, lane = tid & 31;
    const int wm = warp >> 1, wn = warp & 1;

    const uint32_t asBase = (uint32_t)__cvta_generic_to_shared(sA);
    const uint32_t bsBase = (uint32_t)__cvta_generic_to_shared(sB);

    float facc[2][4][4];     // fp32 shadow accumulators
    uint32_t hacc[2][4][2];  // fp16 running accumulators (f16x2 pairs)
    #pragma unroll
    for (int i = 0; i < 2; ++i)
        #pragma unroll
        for (int j = 0; j < 4; ++j) {
            #pragma unroll
            for (int k = 0; k < 4; ++k) facc[i][j][k] = 0.f;
            hacc[i][j][0] = 0u; hacc[i][j][1] = 0u;
        }

    const int a_r = tid >> 2, a_c = (tid & 3) * 8;
    const int b_r = tid >> 3, b_c = (tid & 7) * 8;
    const __half* gA0 = g_xh + (size_t)(bm * BM + a_r) * Dn + a_c;
    const __half* gA1 = gA0 + (size_t)64 * Dn;
    const __half* gB0 = g_w1h + (size_t)b_r * Rn + bn * BN + b_c;

    const uint32_t adst0 = asBase + 2u * (uint32_t)(a_r * ASTR + a_c);
    const uint32_t adst1 = asBase + 2u * (uint32_t)((a_r + 64) * ASTR + a_c);
    const uint32_t bdst0 = bsBase + 2u * (uint32_t)(b_r * BSTR + b_c);

    uint32_t abase[2], bbase[2];
    #pragma unroll
    for (int im = 0; im < 2; ++im)
        abase[im] = asBase + 2u * (uint32_t)((wm * 32 + im * 16 + (lane & 15)) * ASTR
                                             + ((lane >> 4) << 3));
    #pragma unroll
    for (int jn = 0; jn < 2; ++jn)
        bbase[jn] = bsBase + 2u * (uint32_t)((lane & 15) * BSTR
                                             + wn * 32 + jn * 16 + ((lane >> 4) << 3));

    constexpr int KT = Dn / BK;  // 64

    auto load_stage = [&](int kt, int stg) {
        const int k0 = kt * BK;
        const uint32_t ao = 2u * (uint32_t)(stg * A_BUF);
        const uint32_t bo = 2u * (uint32_t)(stg * B_BUF);
        cp_async16(adst0 + ao, gA0 + k0);
        cp_async16(adst1 + ao, gA1 + k0);
        cp_async16(bdst0 + bo, gB0 + (size_t)k0 * Rn);
    };

    load_stage(0, 0); CP_COMMIT();
    load_stage(1, 1); CP_COMMIT();
    load_stage(2, 2); CP_COMMIT();

    for (int kt0 = 0; kt0 < KT; kt0 += 8) {
        #pragma unroll
        for (int si = 0; si < 8; ++si) {
            const int kt = kt0 + si;
            const int s = kt & 3;
            asm volatile("cp.async.wait_group 2;\n" ::);
            __syncthreads();
            if (kt + 3 < KT) load_stage(kt + 3, (kt + 3) & 3);
            CP_COMMIT();

            const uint32_t aoff0 = 2u * (uint32_t)(s * A_BUF);
            const uint32_t aoff1 = 2u * (uint32_t)(s * A_BUF + 16);
            const uint32_t boff0 = 2u * (uint32_t)(s * B_BUF);
            const uint32_t boff1 = 2u * (uint32_t)(s * B_BUF + 16 * BSTR);

            uint32_t ra[2][2][4];  // [ks][im]
            #pragma unroll
            for (int im = 0; im < 2; ++im)
                asm volatile("ldmatrix.sync.aligned.m8n8.x4.shared.b16 {%0,%1,%2,%3}, [%4];"
                    : "=r"(ra[0][im][0]), "=r"(ra[0][im][1]), "=r"(ra[0][im][2]), "=r"(ra[0][im][3])
                    : "r"(abase[im] + aoff0));
            #pragma unroll
            for (int im = 0; im < 2; ++im)
                asm volatile("ldmatrix.sync.aligned.m8n8.x4.shared.b16 {%0,%1,%2,%3}, [%4];"
                    : "=r"(ra[1][im][0]), "=r"(ra[1][im][1]), "=r"(ra[1][im][2]), "=r"(ra[1][im][3])
                    : "r"(abase[im] + aoff1));

            uint32_t rb[2][4];
            #pragma unroll
            for (int jn = 0; jn < 2; ++jn)
                asm volatile("ldmatrix.sync.aligned.m8n8.x4.trans.shared.b16 {%0,%1,%2,%3}, [%4];"
                    : "=r"(rb[jn][0]), "=r"(rb[jn][1]), "=r"(rb[jn][2]), "=r"(rb[jn][3])
                    : "r"(bbase[jn] + boff0));
            #pragma unroll
            for (int im = 0; im < 2; ++im)
                #pragma unroll
                for (int jn = 0; jn < 2; ++jn) {
                    mma16816_f16(hacc[im][jn * 2 + 0], ra[0][im], rb[jn][0], rb[jn][1]);
                    mma16816_f16(hacc[im][jn * 2 + 1], ra[0][im], rb[jn][2], rb[jn][3]);
                }

            #pragma unroll
            for (int jn = 0; jn < 2; ++jn)
                asm volatile("ldmatrix.sync.aligned.m8n8.x4.trans.shared.b16 {%0,%1,%2,%3}, [%4];"
                    : "=r"(rb[jn][0]), "=r"(rb[jn][1]), "=r"(rb[jn][2]), "=r"(rb[jn][3])
                    : "r"(bbase[jn] + boff1));
            #pragma unroll
            for (int im = 0; im < 2; ++im)
                #pragma unroll
                for (int jn = 0; jn < 2; ++jn) {
                    mma16816_f16(hacc[im][jn * 2 + 0], ra[1][im], rb[jn][0], rb[jn][1]);
                    mma16816_f16(hacc[im][jn * 2 + 1], ra[1][im], rb[jn][2], rb[jn][3]);
                }
        }
        // promote fp16 window partials into fp32 shadow, reset fp16 accumulators
        #pragma unroll
        for (int im = 0; im < 2; ++im)
            #pragma unroll
            for (int j = 0; j < 4; ++j) {
                float2 lo = __half22float2(*reinterpret_cast<__half2*>(&hacc[im][j][0]));
                float2 hi = __half22float2(*reinterpret_cast<__half2*>(&hacc[im][j][1]));
                facc[im][j][0] += lo.x; facc[im][j][1] += lo.y;
                facc[im][j][2] += hi.x; facc[im][j][3] += hi.y;
                hacc[im][j][0] = 0u; hacc[im][j][1] = 0u;
            }
    }
    __syncthreads();

    // Epilogue: bias + GELU + warp-level column sums
    const int tq = lane & 3;
    const int batch = bm >> 4;
    #pragma unroll
    for (int j = 0; j < 4; ++j) {
        const int gc = bn * BN + wn * 32 + j * 8 + tq * 2;
        const float bi0 = __ldg(b1 + gc), bi1 = __ldg(b1 + gc + 1);
        float s0 = 0.f, s1 = 0.f;
        #pragma unroll
        for (int im = 0; im < 2; ++im) {
            s0 += gelu_exact(facc[im][j][0] + bi0) + gelu_exact(facc[im][j][2] + bi0);
            s1 += gelu_exact(facc[im][j][1] + bi1) + gelu_exact(facc[im][j][3] + bi1);
        }
        #pragma unroll
        for (int o = 4; o <= 16; o <<= 1) {
            s0 += __shfl_xor_sync(0xFFFFFFFFu, s0, o);
            s1 += __shfl_xor_sync(0xFFFFFFFFu, s1, o);
        }
        if (lane < 4) {
            part[wm][wn * 32 + j * 8 + lane * 2]     = s0;
            part[wm][wn * 32 + j * 8 + lane * 2 + 1] = s1;
        }
    }
    __syncthreads();
    if (tid < BN) {
        float s = part[0][tid] + part[1][tid] + part[2][tid] + part[3][tid];
        atomicAdd(&g_H[batch * Rn + bn * BN + tid], s);
    }
}

// ---------------------------------------------------------------------------
// Kernel 3: T += H @ w2  (K-split)  grid (col8, batch8, kseg4) x 256 threads
// ---------------------------------------------------------------------------
__global__ void tail_kernel(const float* __restrict__ w2) {
    __shared__ float sH[128];
    __shared__ float part[4][64];
    const int b  = blockIdx.y;
    const int c0 = blockIdx.x * 64;
    const int k0 = blockIdx.z * 128;
    const int tid = threadIdx.x;
    if (tid < 128) sH[tid] = g_H[b * Rn + k0 + tid];
    __syncthreads();
    const int col = tid & 63, ks = tid >> 6;
    float a = 0.f;
    const float* w2p = w2 + (size_t)(k0 + ks * 32) * Rn + c0 + col;
    #pragma unroll 8
    for (int r = 0; r < 32; ++r)
        a = fmaf(sH[ks * 32 + r], w2p[(size_t)r * Rn], a);
    part[ks][col] = a;
    __syncthreads();
    if (tid < 64) {
        float t = part[0][tid] + part[1][tid] + part[2][tid] + part[3][tid];
        atomicAdd(&g_T[b * Rn + c0 + tid], t);
    }
}

// ---------------------------------------------------------------------------
// Kernel 4: logits = T @ wr + br ; aux loss + mode
//   1 block x 512 threads; g_T and wr staged in smem (1024 float4 each ->
//   2 float4 per thread), warp-per-4-pairs shfl reduce.
// ---------------------------------------------------------------------------
__global__ __launch_bounds__(512) void final_kernel(const float* __restrict__ wr,
                                                    const float* __restrict__ br,
                                                    float* out, int out_size) {
    __shared__ float sT[Bn * Rn];   // 4096 floats = 1024 float4
    __shared__ float sW[Rn * En];   // 4096 floats = 1024 float4
    __shared__ float sl[Bn * En];   // 64 logits
    const int tid = threadIdx.x;

    // cooperative stage: 2 float4 per thread from each matrix
    {
        const float4* gT4 = reinterpret_cast<const float4*>(g_T);
        const float4* gW4 = reinterpret_cast<const float4*>(wr);
        float4* sT4 = reinterpret_cast<float4*>(sT);
        float4* sW4 = reinterpret_cast<float4*>(sW);
        #pragma unroll
        for (int i = 0; i < 2; ++i) {          // 512 threads x 2 = 1024 float4
            sT4[tid + 512 * i] = gT4[tid + 512 * i];
            sW4[tid + 512 * i] = gW4[tid + 512 * i];
        }
    }
    __syncthreads();

    // 16 warps x 4 pairs each = 64 (b,e) pairs
    const int w = tid >> 5, l = tid & 31;
    #pragma unroll
    for (int pi = 0; pi < 4; ++pi) {
        const int p = w * 4 + pi;
        const int b = p >> 3, e = p & 7;
        float a = 0.f;
        #pragma unroll
        for (int i = 0; i < 16; ++i) {
            const int q = l + 32 * i;
            a = fmaf(sT[b * Rn + q], sW[q * En + e], a);
        }
        #pragma unroll
        for (int o = 16; o; o >>= 1) a += __shfl_xor_sync(0xFFFFFFFFu, a, o);
        if (l == 0) sl[p] = a + br[e];
    }
    __syncthreads();

    if (tid == 0) {
        float aux = 0.f;
        int counts[En] = {};
        for (int b = 0; b < Bn; ++b) {
            const float* lg = &sl[b * En];
            int best = 0;
            for (int e = 1; e < En; ++e)
                if (lg[e] > lg[best]) best = e;
            counts[best]++;
            for (int e = 0; e < En; ++e) {
                float x = lg[e];
                float sp = fmaxf(x, 0.f) + log1pf(expf(-fabsf(x)));
                aux += sp - (e == best ? x : 0.f);
            }
        }
        aux *= (1.f / (Bn * En));
        int nxt = 0;
        for (int e = 1; e < En; ++e)
            if (counts[e] > counts[nxt]) nxt = e;
        out[0] = aux;
        if (out_size > 1) out[1] = (float)nxt;
    }
}

// ---------------------------------------------------------------------------
extern "C" void kernel_launch(void* const* d_in, const int* in_sizes, int n_in,
                              void* d_out, int out_size) {
    const float* hs    = (const float*)d_in[0];
    const float* gamma = (const float*)d_in[1];
    const float* beta  = (const float*)d_in[2];
    const float* w1    = (const float*)d_in[3];
    const float* b1    = (const float*)d_in[4];
    const float* w2    = (const float*)d_in[5];
    const float* b2    = (const float*)d_in[6];
    const float* wr    = (const float*)d_in[7];
    const float* br    = (const float*)d_in[8];

    cudaFuncSetAttribute(gemm_kernel, cudaFuncAttributeMaxDynamicSharedMemorySize, SMEM_BYTES);

    ln_fused_kernel<<<Mn / 8, 256>>>(hs, gamma, beta, w1, b2);     // idx 0
    gemm_kernel<<<dim3(Rn / BN, Mn / BM), 256, SMEM_BYTES>>>(b1);  // idx 1
    tail_kernel<<<dim3(8, Bn, 4), 256>>>(w2);                      // idx 2
    final_kernel<<<1, 512>>>(wr, br, (float*)d_out, out_size);     // idx 3
}